// round 2
// baseline (speedup 1.0000x reference)
#include <cuda_runtime.h>

// Problem constants
constexpr int NN  = 50000;   // nodes
constexpr int NE  = 800000;  // edges
constexpr int ND  = 64;      // node dim
constexpr int ED  = 64;      // edge dim
constexpr int HID = 128;     // hidden

// Scratch (device globals: allocation-free)
__device__ float g_PR[NN * HID];   // x @ eW1[64:128]   (source-node term)
__device__ float g_PC[NN * HID];   // x @ eW1[128:192]  (dest-node term)
__device__ float g_msg[NN * ED];   // scatter-add accumulator

// ---------------------------------------------------------------------------
// Zero the message accumulator (float4 = 800000 vecs)
// ---------------------------------------------------------------------------
__global__ void zero_msg_kernel() {
    int i = blockIdx.x * blockDim.x + threadIdx.x;  // grid covers NN*ED/4
    reinterpret_cast<float4*>(g_msg)[i] = make_float4(0.f, 0.f, 0.f, 0.f);
}

// ---------------------------------------------------------------------------
// Precompute PR/PC: GEMM [NN,64] @ [64,256] (256 cols = PR|PC concatenated)
// Tile: 64 nodes x 256 cols, 256 threads, each thread 4 rows x 16 cols.
// ---------------------------------------------------------------------------
__global__ void __launch_bounds__(256) precompute_kernel(
    const float* __restrict__ x, const float* __restrict__ eW1)
{
    extern __shared__ float sm[];
    float* Xs = sm;               // [64][68] padded
    float* Ws = sm + 64 * 68;     // [64][256]

    const int n0 = blockIdx.x * 64;
    const int tid = threadIdx.x;

    for (int idx = tid; idx < 64 * 64; idx += 256) {
        int r = idx >> 6, c = idx & 63;
        int n = n0 + r;
        Xs[r * 68 + c] = (n < NN) ? x[n * 64 + c] : 0.f;
    }
    // Ws[k][j]: j<128 -> eW1[(64+k)][j] (PR), else eW1[(128+k)][j-128] (PC)
    for (int idx = tid; idx < 64 * 256; idx += 256) {
        int k = idx >> 8, j = idx & 255;
        float v = (j < 128) ? eW1[(64 + k) * 128 + j]
                            : eW1[(128 + k) * 128 + (j - 128)];
        Ws[k * 256 + j] = v;
    }
    __syncthreads();

    const int tx = tid & 15;   // 16 col-groups of 16
    const int ty = tid >> 4;   // 16 row-groups of 4

    float acc[4][16];
    #pragma unroll
    for (int i = 0; i < 4; i++)
        #pragma unroll
        for (int j = 0; j < 16; j++) acc[i][j] = 0.f;

    #pragma unroll 4
    for (int k = 0; k < 64; k++) {
        float a[4];
        #pragma unroll
        for (int i = 0; i < 4; i++) a[i] = Xs[(ty * 4 + i) * 68 + k];
        const float4 b0 = *(const float4*)&Ws[k * 256 + tx * 16 + 0];
        const float4 b1 = *(const float4*)&Ws[k * 256 + tx * 16 + 4];
        const float4 b2 = *(const float4*)&Ws[k * 256 + tx * 16 + 8];
        const float4 b3 = *(const float4*)&Ws[k * 256 + tx * 16 + 12];
        float b[16] = {b0.x, b0.y, b0.z, b0.w, b1.x, b1.y, b1.z, b1.w,
                       b2.x, b2.y, b2.z, b2.w, b3.x, b3.y, b3.z, b3.w};
        #pragma unroll
        for (int i = 0; i < 4; i++)
            #pragma unroll
            for (int j = 0; j < 16; j++)
                acc[i][j] = fmaf(a[i], b[j], acc[i][j]);
    }

    float* dst  = (tx < 8) ? g_PR : g_PC;
    int    cb   = (tx < 8) ? tx * 16 : (tx - 8) * 16;
    #pragma unroll
    for (int i = 0; i < 4; i++) {
        int n = n0 + ty * 4 + i;
        if (n >= NN) continue;
        #pragma unroll
        for (int j = 0; j < 16; j += 4) {
            float4 o = make_float4(acc[i][j], acc[i][j + 1],
                                   acc[i][j + 2], acc[i][j + 3]);
            *(float4*)&dst[n * 128 + cb + j] = o;
        }
    }
}

// ---------------------------------------------------------------------------
// Edge kernel: per 64-edge tile:
//   H = relu(edge_attr@eW1[0:64] + PR[row] + PC[col] + eb1)   [64 x 128]
//   out = H @ eW2 + eb2                                       [64 x 64]
//   write out_edge, atomicAdd into g_msg[col]
// ---------------------------------------------------------------------------
__global__ void __launch_bounds__(256) edge_kernel(
    const float* __restrict__ edge_attr,
    const int*   __restrict__ edge_index,   // [2][NE]
    const float* __restrict__ eW1,
    const float* __restrict__ eb1,
    const float* __restrict__ eW2,
    const float* __restrict__ eb2,
    float* __restrict__ out_edge)
{
    extern __shared__ float sm[];
    float* As  = sm;                     // [64][68]
    float* W1s = As  + 64 * 68;          // [64][128]
    float* Hs  = W1s + 64 * 128;         // [64][132]
    float* W2s = Hs  + 64 * 132;         // [128][64]

    const int e0  = blockIdx.x * 64;
    const int tid = threadIdx.x;

    for (int idx = tid; idx < 64 * 64; idx += 256) {
        int r = idx >> 6, c = idx & 63;
        As[r * 68 + c] = edge_attr[(e0 + r) * 64 + c];
    }
    for (int idx = tid; idx < 64 * 128; idx += 256)
        W1s[idx] = eW1[idx];             // rows 0..63 of eW1, contiguous
    for (int idx = tid; idx < 128 * 64; idx += 256)
        W2s[idx] = eW2[idx];
    __syncthreads();

    const int tx = tid & 15;  // col group
    const int ty = tid >> 4;  // row group (4 edges)

    // ---- layer 1: 4x8 micro-tile, K=64 ----
    float acc[4][8];
    #pragma unroll
    for (int i = 0; i < 4; i++)
        #pragma unroll
        for (int j = 0; j < 8; j++) acc[i][j] = 0.f;

    #pragma unroll 4
    for (int k = 0; k < 64; k++) {
        float a[4];
        #pragma unroll
        for (int i = 0; i < 4; i++) a[i] = As[(ty * 4 + i) * 68 + k];
        const float4 b0 = *(const float4*)&W1s[k * 128 + tx * 8 + 0];
        const float4 b1 = *(const float4*)&W1s[k * 128 + tx * 8 + 4];
        float b[8] = {b0.x, b0.y, b0.z, b0.w, b1.x, b1.y, b1.z, b1.w};
        #pragma unroll
        for (int i = 0; i < 4; i++)
            #pragma unroll
            for (int j = 0; j < 8; j++)
                acc[i][j] = fmaf(a[i], b[j], acc[i][j]);
    }

    // epilogue: + eb1 + PR[row] + PC[col], relu -> Hs
    int rsrc[4], cdst[4];
    #pragma unroll
    for (int i = 0; i < 4; i++) {
        int e = e0 + ty * 4 + i;
        rsrc[i] = edge_index[e];
        cdst[i] = edge_index[NE + e];
    }
    const float4 e1a = *(const float4*)&eb1[tx * 8 + 0];
    const float4 e1b = *(const float4*)&eb1[tx * 8 + 4];
    float bias1[8] = {e1a.x, e1a.y, e1a.z, e1a.w, e1b.x, e1b.y, e1b.z, e1b.w};

    #pragma unroll
    for (int i = 0; i < 4; i++) {
        const float4 pr0 = *(const float4*)&g_PR[rsrc[i] * 128 + tx * 8 + 0];
        const float4 pr1 = *(const float4*)&g_PR[rsrc[i] * 128 + tx * 8 + 4];
        const float4 pc0 = *(const float4*)&g_PC[cdst[i] * 128 + tx * 8 + 0];
        const float4 pc1 = *(const float4*)&g_PC[cdst[i] * 128 + tx * 8 + 4];
        float g[8] = {pr0.x + pc0.x, pr0.y + pc0.y, pr0.z + pc0.z, pr0.w + pc0.w,
                      pr1.x + pc1.x, pr1.y + pc1.y, pr1.z + pc1.z, pr1.w + pc1.w};
        float h[8];
        #pragma unroll
        for (int j = 0; j < 8; j++) {
            float v = acc[i][j] + bias1[j] + g[j];
            h[j] = v > 0.f ? v : 0.f;
        }
        float* hp = &Hs[(ty * 4 + i) * 132 + tx * 8];
        *(float4*)(hp + 0) = make_float4(h[0], h[1], h[2], h[3]);
        *(float4*)(hp + 4) = make_float4(h[4], h[5], h[6], h[7]);
    }
    __syncthreads();

    // ---- layer 2: 4x4 micro-tile, K=128 ----
    float acc2[4][4];
    #pragma unroll
    for (int i = 0; i < 4; i++)
        #pragma unroll
        for (int j = 0; j < 4; j++) acc2[i][j] = 0.f;

    #pragma unroll 4
    for (int k = 0; k < 128; k++) {
        float a[4];
        #pragma unroll
        for (int i = 0; i < 4; i++) a[i] = Hs[(ty * 4 + i) * 132 + k];
        const float4 b = *(const float4*)&W2s[k * 64 + tx * 4];
        #pragma unroll
        for (int i = 0; i < 4; i++) {
            acc2[i][0] = fmaf(a[i], b.x, acc2[i][0]);
            acc2[i][1] = fmaf(a[i], b.y, acc2[i][1]);
            acc2[i][2] = fmaf(a[i], b.z, acc2[i][2]);
            acc2[i][3] = fmaf(a[i], b.w, acc2[i][3]);
        }
    }

    const float4 b2 = *(const float4*)&eb2[tx * 4];
    #pragma unroll
    for (int i = 0; i < 4; i++) {
        int e = e0 + ty * 4 + i;
        float4 o = make_float4(acc2[i][0] + b2.x, acc2[i][1] + b2.y,
                               acc2[i][2] + b2.z, acc2[i][3] + b2.w);
        *(float4*)&out_edge[e * 64 + tx * 4] = o;
        float* mp = &g_msg[cdst[i] * 64 + tx * 4];
        atomicAdd(mp + 0, o.x);
        atomicAdd(mp + 1, o.y);
        atomicAdd(mp + 2, o.z);
        atomicAdd(mp + 3, o.w);
    }
}

// ---------------------------------------------------------------------------
// Node kernel: x_new = relu([x|msg]@nW1 + nb1) @ nW2 + nb2
// Tile: 64 nodes, 256 threads.
// ---------------------------------------------------------------------------
__global__ void __launch_bounds__(256) node_kernel(
    const float* __restrict__ x,
    const float* __restrict__ nW1, const float* __restrict__ nb1,
    const float* __restrict__ nW2, const float* __restrict__ nb2,
    float* __restrict__ out_node)
{
    extern __shared__ float sm[];
    float* Ins = sm;                      // [64][132]
    float* W1s = Ins + 64 * 132;          // [128][128]
    float* Hs  = W1s + 128 * 128;         // [64][132]
    float* W2s = Hs  + 64 * 132;          // [128][64]

    const int n0  = blockIdx.x * 64;
    const int tid = threadIdx.x;

    for (int idx = tid; idx < 64 * 128; idx += 256) {
        int r = idx >> 7, c = idx & 127;
        int n = n0 + r;
        float v = 0.f;
        if (n < NN) v = (c < 64) ? x[n * 64 + c] : g_msg[n * 64 + (c - 64)];
        Ins[r * 132 + c] = v;
    }
    for (int idx = tid; idx < 128 * 128; idx += 256) W1s[idx] = nW1[idx];
    for (int idx = tid; idx < 128 * 64;  idx += 256) W2s[idx] = nW2[idx];
    __syncthreads();

    const int tx = tid & 15;
    const int ty = tid >> 4;

    // layer 1: K=128
    float acc[4][8];
    #pragma unroll
    for (int i = 0; i < 4; i++)
        #pragma unroll
        for (int j = 0; j < 8; j++) acc[i][j] = 0.f;

    #pragma unroll 4
    for (int k = 0; k < 128; k++) {
        float a[4];
        #pragma unroll
        for (int i = 0; i < 4; i++) a[i] = Ins[(ty * 4 + i) * 132 + k];
        const float4 b0 = *(const float4*)&W1s[k * 128 + tx * 8 + 0];
        const float4 b1 = *(const float4*)&W1s[k * 128 + tx * 8 + 4];
        float b[8] = {b0.x, b0.y, b0.z, b0.w, b1.x, b1.y, b1.z, b1.w};
        #pragma unroll
        for (int i = 0; i < 4; i++)
            #pragma unroll
            for (int j = 0; j < 8; j++)
                acc[i][j] = fmaf(a[i], b[j], acc[i][j]);
    }

    const float4 n1a = *(const float4*)&nb1[tx * 8 + 0];
    const float4 n1b = *(const float4*)&nb1[tx * 8 + 4];
    float bias1[8] = {n1a.x, n1a.y, n1a.z, n1a.w, n1b.x, n1b.y, n1b.z, n1b.w};
    #pragma unroll
    for (int i = 0; i < 4; i++) {
        float h[8];
        #pragma unroll
        for (int j = 0; j < 8; j++) {
            float v = acc[i][j] + bias1[j];
            h[j] = v > 0.f ? v : 0.f;
        }
        float* hp = &Hs[(ty * 4 + i) * 132 + tx * 8];
        *(float4*)(hp + 0) = make_float4(h[0], h[1], h[2], h[3]);
        *(float4*)(hp + 4) = make_float4(h[4], h[5], h[6], h[7]);
    }
    __syncthreads();

    // layer 2: K=128
    float acc2[4][4];
    #pragma unroll
    for (int i = 0; i < 4; i++)
        #pragma unroll
        for (int j = 0; j < 4; j++) acc2[i][j] = 0.f;

    #pragma unroll 4
    for (int k = 0; k < 128; k++) {
        float a[4];
        #pragma unroll
        for (int i = 0; i < 4; i++) a[i] = Hs[(ty * 4 + i) * 132 + k];
        const float4 b = *(const float4*)&W2s[k * 64 + tx * 4];
        #pragma unroll
        for (int i = 0; i < 4; i++) {
            acc2[i][0] = fmaf(a[i], b.x, acc2[i][0]);
            acc2[i][1] = fmaf(a[i], b.y, acc2[i][1]);
            acc2[i][2] = fmaf(a[i], b.z, acc2[i][2]);
            acc2[i][3] = fmaf(a[i], b.w, acc2[i][3]);
        }
    }

    const float4 b2 = *(const float4*)&nb2[tx * 4];
    #pragma unroll
    for (int i = 0; i < 4; i++) {
        int n = n0 + ty * 4 + i;
        if (n >= NN) continue;
        float4 o = make_float4(acc2[i][0] + b2.x, acc2[i][1] + b2.y,
                               acc2[i][2] + b2.z, acc2[i][3] + b2.w);
        *(float4*)&out_node[n * 64 + tx * 4] = o;
    }
}

// ---------------------------------------------------------------------------
extern "C" void kernel_launch(void* const* d_in, const int* in_sizes, int n_in,
                              void* d_out, int out_size)
{
    const float* x    = (const float*)d_in[0];
    const int*   ei   = (const int*)  d_in[1];
    const float* ea   = (const float*)d_in[2];
    const float* eW1  = (const float*)d_in[3];
    const float* eb1  = (const float*)d_in[4];
    const float* eW2  = (const float*)d_in[5];
    const float* eb2  = (const float*)d_in[6];
    const float* nW1  = (const float*)d_in[7];
    const float* nb1  = (const float*)d_in[8];
    const float* nW2  = (const float*)d_in[9];
    const float* nb2  = (const float*)d_in[10];

    float* out_node = (float*)d_out;             // [NN, 64]
    float* out_edge = (float*)d_out + NN * ND;   // [NE, 64]

    const int smem_pre  = (64 * 68 + 64 * 256) * 4;                         // 82944
    const int smem_edge = (64 * 68 + 64 * 128 + 64 * 132 + 128 * 64) * 4;   // 116736
    const int smem_node = (64 * 132 + 128 * 128 + 64 * 132 + 128 * 64) * 4; // 165888

    cudaFuncSetAttribute(precompute_kernel,
        cudaFuncAttributeMaxDynamicSharedMemorySize, smem_pre);
    cudaFuncSetAttribute(edge_kernel,
        cudaFuncAttributeMaxDynamicSharedMemorySize, smem_edge);
    cudaFuncSetAttribute(node_kernel,
        cudaFuncAttributeMaxDynamicSharedMemorySize, smem_node);

    zero_msg_kernel<<<(NN * ED / 4) / 256, 256>>>();
    precompute_kernel<<<(NN + 63) / 64, 256, smem_pre>>>(x, eW1);
    edge_kernel<<<NE / 64, 256, smem_edge>>>(ea, ei, eW1, eb1, eW2, eb2, out_edge);
    node_kernel<<<(NN + 63) / 64, 256, smem_node>>>(x, nW1, nb1, nW2, nb2, out_node);
}

// round 3
// speedup vs baseline: 1.4537x; 1.4537x over previous
#include <cuda_runtime.h>

// Problem constants
constexpr int NN  = 50000;   // nodes
constexpr int NE  = 800000;  // edges
constexpr int ND  = 64;      // node dim
constexpr int ED  = 64;      // edge dim
constexpr int HID = 128;     // hidden

// Scratch (device globals: allocation-free)
__device__ float g_PR[NN * HID];   // x @ eW1[64:128]   (source-node term)
__device__ float g_PC[NN * HID];   // x @ eW1[128:192]  (dest-node term)
__device__ float g_msg[NN * ED];   // scatter-add accumulator

// ---------------------------------------------------------------------------
// Zero the message accumulator
// ---------------------------------------------------------------------------
__global__ void zero_msg_kernel() {
    int i = blockIdx.x * blockDim.x + threadIdx.x;
    reinterpret_cast<float4*>(g_msg)[i] = make_float4(0.f, 0.f, 0.f, 0.f);
}

// ---------------------------------------------------------------------------
// Precompute PR/PC: GEMM [NN,64] @ [64,256] (256 cols = PR|PC concatenated)
// ---------------------------------------------------------------------------
__global__ void __launch_bounds__(256, 2) precompute_kernel(
    const float* __restrict__ x, const float* __restrict__ eW1)
{
    extern __shared__ float sm[];
    float* Xs = sm;               // [64][68] padded
    float* Ws = sm + 64 * 68;     // [64][256]

    const int n0 = blockIdx.x * 64;
    const int tid = threadIdx.x;

    for (int idx = tid; idx < 64 * 64; idx += 256) {
        int r = idx >> 6, c = idx & 63;
        int n = n0 + r;
        Xs[r * 68 + c] = (n < NN) ? x[n * 64 + c] : 0.f;
    }
    for (int idx = tid; idx < 64 * 256; idx += 256) {
        int k = idx >> 8, j = idx & 255;
        float v = (j < 128) ? eW1[(64 + k) * 128 + j]
                            : eW1[(128 + k) * 128 + (j - 128)];
        Ws[k * 256 + j] = v;
    }
    __syncthreads();

    const int tx = tid & 15;
    const int ty = tid >> 4;

    float acc[4][16];
    #pragma unroll
    for (int i = 0; i < 4; i++)
        #pragma unroll
        for (int j = 0; j < 16; j++) acc[i][j] = 0.f;

    #pragma unroll 4
    for (int k = 0; k < 64; k++) {
        float a[4];
        #pragma unroll
        for (int i = 0; i < 4; i++) a[i] = Xs[(ty * 4 + i) * 68 + k];
        const float4 b0 = *(const float4*)&Ws[k * 256 + tx * 16 + 0];
        const float4 b1 = *(const float4*)&Ws[k * 256 + tx * 16 + 4];
        const float4 b2 = *(const float4*)&Ws[k * 256 + tx * 16 + 8];
        const float4 b3 = *(const float4*)&Ws[k * 256 + tx * 16 + 12];
        float b[16] = {b0.x, b0.y, b0.z, b0.w, b1.x, b1.y, b1.z, b1.w,
                       b2.x, b2.y, b2.z, b2.w, b3.x, b3.y, b3.z, b3.w};
        #pragma unroll
        for (int i = 0; i < 4; i++)
            #pragma unroll
            for (int j = 0; j < 16; j++)
                acc[i][j] = fmaf(a[i], b[j], acc[i][j]);
    }

    float* dst  = (tx < 8) ? g_PR : g_PC;
    int    cb   = (tx < 8) ? tx * 16 : (tx - 8) * 16;
    #pragma unroll
    for (int i = 0; i < 4; i++) {
        int n = n0 + ty * 4 + i;
        if (n >= NN) continue;
        #pragma unroll
        for (int j = 0; j < 16; j += 4) {
            float4 o = make_float4(acc[i][j], acc[i][j + 1],
                                   acc[i][j + 2], acc[i][j + 3]);
            *(float4*)&dst[n * 128 + cb + j] = o;
        }
    }
}

// ---------------------------------------------------------------------------
// Edge kernel, 64 edges/block, 256 threads, smem ~99KB -> 2 blocks/SM.
// buf is UNIONED: As (layer-1 input) then Hs (layer-2 input).
// ---------------------------------------------------------------------------
__global__ void __launch_bounds__(256, 2) edge_kernel(
    const float* __restrict__ edge_attr,
    const int*   __restrict__ edge_index,   // [2][NE]
    const float* __restrict__ eW1,
    const float* __restrict__ eb1,
    const float* __restrict__ eW2,
    const float* __restrict__ eb2,
    float* __restrict__ out_edge)
{
    extern __shared__ float sm[];
    float* buf = sm;                     // [64][132]  As then Hs
    float* W1s = buf + 64 * 132;         // [64][128]
    float* W2s = W1s + 64 * 128;         // [128][64]

    const int e0  = blockIdx.x * 64;
    const int tid = threadIdx.x;

    for (int idx = tid; idx < 64 * 64; idx += 256) {
        int r = idx >> 6, c = idx & 63;
        buf[r * 132 + c] = edge_attr[(e0 + r) * 64 + c];
    }
    for (int idx = tid; idx < 64 * 128; idx += 256)
        W1s[idx] = eW1[idx];             // rows 0..63 of eW1
    for (int idx = tid; idx < 128 * 64; idx += 256)
        W2s[idx] = eW2[idx];
    __syncthreads();

    const int tx = tid & 15;  // col group
    const int ty = tid >> 4;  // row group (4 edges)

    // ---- layer 1: 4x8 micro-tile, K=64 ----
    float acc[4][8];
    #pragma unroll
    for (int i = 0; i < 4; i++)
        #pragma unroll
        for (int j = 0; j < 8; j++) acc[i][j] = 0.f;

    #pragma unroll 4
    for (int k = 0; k < 64; k++) {
        float a[4];
        #pragma unroll
        for (int i = 0; i < 4; i++) a[i] = buf[(ty * 4 + i) * 132 + k];
        const float4 b0 = *(const float4*)&W1s[k * 128 + tx * 8 + 0];
        const float4 b1 = *(const float4*)&W1s[k * 128 + tx * 8 + 4];
        float b[8] = {b0.x, b0.y, b0.z, b0.w, b1.x, b1.y, b1.z, b1.w};
        #pragma unroll
        for (int i = 0; i < 4; i++)
            #pragma unroll
            for (int j = 0; j < 8; j++)
                acc[i][j] = fmaf(a[i], b[j], acc[i][j]);
    }

    // epilogue: + eb1 + PR[row] + PC[col], relu
    int rsrc[4], cdst[4];
    #pragma unroll
    for (int i = 0; i < 4; i++) {
        int e = e0 + ty * 4 + i;
        rsrc[i] = edge_index[e];
        cdst[i] = edge_index[NE + e];
    }
    const float4 e1a = *(const float4*)&eb1[tx * 8 + 0];
    const float4 e1b = *(const float4*)&eb1[tx * 8 + 4];
    float bias1[8] = {e1a.x, e1a.y, e1a.z, e1a.w, e1b.x, e1b.y, e1b.z, e1b.w};

    float h[4][8];
    #pragma unroll
    for (int i = 0; i < 4; i++) {
        const float4 pr0 = *(const float4*)&g_PR[rsrc[i] * 128 + tx * 8 + 0];
        const float4 pr1 = *(const float4*)&g_PR[rsrc[i] * 128 + tx * 8 + 4];
        const float4 pc0 = *(const float4*)&g_PC[cdst[i] * 128 + tx * 8 + 0];
        const float4 pc1 = *(const float4*)&g_PC[cdst[i] * 128 + tx * 8 + 4];
        float g[8] = {pr0.x + pc0.x, pr0.y + pc0.y, pr0.z + pc0.z, pr0.w + pc0.w,
                      pr1.x + pc1.x, pr1.y + pc1.y, pr1.z + pc1.z, pr1.w + pc1.w};
        #pragma unroll
        for (int j = 0; j < 8; j++) {
            float v = acc[i][j] + bias1[j] + g[j];
            h[i][j] = v > 0.f ? v : 0.f;
        }
    }

    // all reads of As are done; reuse buf as Hs
    __syncthreads();
    #pragma unroll
    for (int i = 0; i < 4; i++) {
        float* hp = &buf[(ty * 4 + i) * 132 + tx * 8];
        *(float4*)(hp + 0) = make_float4(h[i][0], h[i][1], h[i][2], h[i][3]);
        *(float4*)(hp + 4) = make_float4(h[i][4], h[i][5], h[i][6], h[i][7]);
    }
    __syncthreads();

    // ---- layer 2: 4x4 micro-tile, K=128 ----
    float acc2[4][4];
    #pragma unroll
    for (int i = 0; i < 4; i++)
        #pragma unroll
        for (int j = 0; j < 4; j++) acc2[i][j] = 0.f;

    #pragma unroll 4
    for (int k = 0; k < 128; k++) {
        float a[4];
        #pragma unroll
        for (int i = 0; i < 4; i++) a[i] = buf[(ty * 4 + i) * 132 + k];
        const float4 b = *(const float4*)&W2s[k * 64 + tx * 4];
        #pragma unroll
        for (int i = 0; i < 4; i++) {
            acc2[i][0] = fmaf(a[i], b.x, acc2[i][0]);
            acc2[i][1] = fmaf(a[i], b.y, acc2[i][1]);
            acc2[i][2] = fmaf(a[i], b.z, acc2[i][2]);
            acc2[i][3] = fmaf(a[i], b.w, acc2[i][3]);
        }
    }

    const float4 b2 = *(const float4*)&eb2[tx * 4];
    #pragma unroll
    for (int i = 0; i < 4; i++) {
        int e = e0 + ty * 4 + i;
        float4 o = make_float4(acc2[i][0] + b2.x, acc2[i][1] + b2.y,
                               acc2[i][2] + b2.z, acc2[i][3] + b2.w);
        *(float4*)&out_edge[e * 64 + tx * 4] = o;
        float* mp = &g_msg[cdst[i] * 64 + tx * 4];
        atomicAdd(mp + 0, o.x);
        atomicAdd(mp + 1, o.y);
        atomicAdd(mp + 2, o.z);
        atomicAdd(mp + 3, o.w);
    }
}

// ---------------------------------------------------------------------------
// Node kernel: x_new = relu([x|msg]@nW1 + nb1) @ nW2 + nb2
// nW1 staged in two K=64 halves; buf unioned (Ins then Hs). smem ~99KB.
// ---------------------------------------------------------------------------
__global__ void __launch_bounds__(256, 2) node_kernel(
    const float* __restrict__ x,
    const float* __restrict__ nW1, const float* __restrict__ nb1,
    const float* __restrict__ nW2, const float* __restrict__ nb2,
    float* __restrict__ out_node)
{
    extern __shared__ float sm[];
    float* buf = sm;                      // [64][132]  Ins then Hs
    float* W1s = buf + 64 * 132;          // [64][128]  (one K-half of nW1)
    float* W2s = W1s + 64 * 128;          // [128][64]

    const int n0  = blockIdx.x * 64;
    const int tid = threadIdx.x;

    for (int idx = tid; idx < 64 * 128; idx += 256) {
        int r = idx >> 7, c = idx & 127;
        int n = n0 + r;
        float v = 0.f;
        if (n < NN) v = (c < 64) ? x[n * 64 + c] : g_msg[n * 64 + (c - 64)];
        buf[r * 132 + c] = v;
    }
    for (int idx = tid; idx < 128 * 64; idx += 256) W2s[idx] = nW2[idx];

    const int tx = tid & 15;
    const int ty = tid >> 4;

    // layer 1: K=128 in two staged halves of nW1
    float acc[4][8];
    #pragma unroll
    for (int i = 0; i < 4; i++)
        #pragma unroll
        for (int j = 0; j < 8; j++) acc[i][j] = 0.f;

    #pragma unroll
    for (int half = 0; half < 2; half++) {
        for (int idx = tid; idx < 64 * 128; idx += 256)
            W1s[idx] = nW1[half * 64 * 128 + idx];
        __syncthreads();

        #pragma unroll 4
        for (int k = 0; k < 64; k++) {
            float a[4];
            #pragma unroll
            for (int i = 0; i < 4; i++)
                a[i] = buf[(ty * 4 + i) * 132 + half * 64 + k];
            const float4 b0 = *(const float4*)&W1s[k * 128 + tx * 8 + 0];
            const float4 b1 = *(const float4*)&W1s[k * 128 + tx * 8 + 4];
            float b[8] = {b0.x, b0.y, b0.z, b0.w, b1.x, b1.y, b1.z, b1.w};
            #pragma unroll
            for (int i = 0; i < 4; i++)
                #pragma unroll
                for (int j = 0; j < 8; j++)
                    acc[i][j] = fmaf(a[i], b[j], acc[i][j]);
        }
        __syncthreads();
    }

    const float4 n1a = *(const float4*)&nb1[tx * 8 + 0];
    const float4 n1b = *(const float4*)&nb1[tx * 8 + 4];
    float bias1[8] = {n1a.x, n1a.y, n1a.z, n1a.w, n1b.x, n1b.y, n1b.z, n1b.w};
    #pragma unroll
    for (int i = 0; i < 4; i++) {
        float h[8];
        #pragma unroll
        for (int j = 0; j < 8; j++) {
            float v = acc[i][j] + bias1[j];
            h[j] = v > 0.f ? v : 0.f;
        }
        float* hp = &buf[(ty * 4 + i) * 132 + tx * 8];
        *(float4*)(hp + 0) = make_float4(h[0], h[1], h[2], h[3]);
        *(float4*)(hp + 4) = make_float4(h[4], h[5], h[6], h[7]);
    }
    __syncthreads();

    // layer 2: K=128
    float acc2[4][4];
    #pragma unroll
    for (int i = 0; i < 4; i++)
        #pragma unroll
        for (int j = 0; j < 4; j++) acc2[i][j] = 0.f;

    #pragma unroll 4
    for (int k = 0; k < 128; k++) {
        float a[4];
        #pragma unroll
        for (int i = 0; i < 4; i++) a[i] = buf[(ty * 4 + i) * 132 + k];
        const float4 b = *(const float4*)&W2s[k * 64 + tx * 4];
        #pragma unroll
        for (int i = 0; i < 4; i++) {
            acc2[i][0] = fmaf(a[i], b.x, acc2[i][0]);
            acc2[i][1] = fmaf(a[i], b.y, acc2[i][1]);
            acc2[i][2] = fmaf(a[i], b.z, acc2[i][2]);
            acc2[i][3] = fmaf(a[i], b.w, acc2[i][3]);
        }
    }

    const float4 b2 = *(const float4*)&nb2[tx * 4];
    #pragma unroll
    for (int i = 0; i < 4; i++) {
        int n = n0 + ty * 4 + i;
        if (n >= NN) continue;
        float4 o = make_float4(acc2[i][0] + b2.x, acc2[i][1] + b2.y,
                               acc2[i][2] + b2.z, acc2[i][3] + b2.w);
        *(float4*)&out_node[n * 64 + tx * 4] = o;
    }
}

// ---------------------------------------------------------------------------
extern "C" void kernel_launch(void* const* d_in, const int* in_sizes, int n_in,
                              void* d_out, int out_size)
{
    const float* x    = (const float*)d_in[0];
    const int*   ei   = (const int*)  d_in[1];
    const float* ea   = (const float*)d_in[2];
    const float* eW1  = (const float*)d_in[3];
    const float* eb1  = (const float*)d_in[4];
    const float* eW2  = (const float*)d_in[5];
    const float* eb2  = (const float*)d_in[6];
    const float* nW1  = (const float*)d_in[7];
    const float* nb1  = (const float*)d_in[8];
    const float* nW2  = (const float*)d_in[9];
    const float* nb2  = (const float*)d_in[10];

    float* out_node = (float*)d_out;             // [NN, 64]
    float* out_edge = (float*)d_out + NN * ND;   // [NE, 64]

    const int smem_pre  = (64 * 68 + 64 * 256) * 4;                 // 82944
    const int smem_edge = (64 * 132 + 64 * 128 + 128 * 64) * 4;     // 99328
    const int smem_node = (64 * 132 + 64 * 128 + 128 * 64) * 4;     // 99328

    cudaFuncSetAttribute(precompute_kernel,
        cudaFuncAttributeMaxDynamicSharedMemorySize, smem_pre);
    cudaFuncSetAttribute(edge_kernel,
        cudaFuncAttributeMaxDynamicSharedMemorySize, smem_edge);
    cudaFuncSetAttribute(node_kernel,
        cudaFuncAttributeMaxDynamicSharedMemorySize, smem_node);

    zero_msg_kernel<<<(NN * ED / 4) / 256, 256>>>();
    precompute_kernel<<<(NN + 63) / 64, 256, smem_pre>>>(x, eW1);
    edge_kernel<<<NE / 64, 256, smem_edge>>>(ea, ei, eW1, eb1, eW2, eb2, out_edge);
    node_kernel<<<(NN + 63) / 64, 256, smem_node>>>(x, nW1, nb1, nW2, nb2, out_node);
}

// round 6
// speedup vs baseline: 2.0374x; 1.4016x over previous
#include <cuda_runtime.h>
#include <cstdint>

// Problem constants
constexpr int NN  = 50000;   // nodes
constexpr int NE  = 800000;  // edges
constexpr int ND  = 64;      // node dim
constexpr int ED  = 64;      // edge dim
constexpr int HID = 128;     // hidden

// Scratch (device globals: allocation-free)
__device__ float g_PR[NN * HID];   // x @ eW1[64:128]   (source-node term, fp32 exact)
__device__ float g_PC[NN * HID];   // x @ eW1[128:192]  (dest-node term, fp32 exact)
__device__ float g_msg[NN * ED];   // scatter-add accumulator

// ---------------------------------------------------------------------------
// helpers
// ---------------------------------------------------------------------------
__device__ __forceinline__ uint32_t f32_to_tf32(float f) {
    uint32_t u;
    asm("cvt.rna.tf32.f32 %0, %1;" : "=r"(u) : "f"(f));
    return u;
}

// D += A@B  (m16n8k8 tf32, row.col), D/C in-place
__device__ __forceinline__ void mma_tf32(float d[4], const uint32_t a[4],
                                         const uint32_t b[2]) {
    asm volatile(
        "mma.sync.aligned.m16n8k8.row.col.f32.tf32.tf32.f32 "
        "{%0,%1,%2,%3}, {%4,%5,%6,%7}, {%8,%9}, {%0,%1,%2,%3};"
        : "+f"(d[0]), "+f"(d[1]), "+f"(d[2]), "+f"(d[3])
        : "r"(a[0]), "r"(a[1]), "r"(a[2]), "r"(a[3]), "r"(b[0]), "r"(b[1]));
}

// ---------------------------------------------------------------------------
// Zero the message accumulator
// ---------------------------------------------------------------------------
__global__ void zero_msg_kernel() {
    int i = blockIdx.x * blockDim.x + threadIdx.x;
    reinterpret_cast<float4*>(g_msg)[i] = make_float4(0.f, 0.f, 0.f, 0.f);
}

// ---------------------------------------------------------------------------
// Precompute PR/PC (fp32 exact): GEMM [NN,64] @ [64,256]
// ---------------------------------------------------------------------------
__global__ void __launch_bounds__(256, 2) precompute_kernel(
    const float* __restrict__ x, const float* __restrict__ eW1)
{
    extern __shared__ float sm[];
    float* Xs = sm;               // [64][68]
    float* Ws = sm + 64 * 68;     // [64][256]

    const int n0 = blockIdx.x * 64;
    const int tid = threadIdx.x;

    for (int idx = tid; idx < 64 * 64; idx += 256) {
        int r = idx >> 6, c = idx & 63;
        int n = n0 + r;
        Xs[r * 68 + c] = (n < NN) ? x[n * 64 + c] : 0.f;
    }
    for (int idx = tid; idx < 64 * 256; idx += 256) {
        int k = idx >> 8, j = idx & 255;
        float v = (j < 128) ? eW1[(64 + k) * 128 + j]
                            : eW1[(128 + k) * 128 + (j - 128)];
        Ws[k * 256 + j] = v;
    }
    __syncthreads();

    const int tx = tid & 15;
    const int ty = tid >> 4;

    float acc[4][16];
    #pragma unroll
    for (int i = 0; i < 4; i++)
        #pragma unroll
        for (int j = 0; j < 16; j++) acc[i][j] = 0.f;

    #pragma unroll 4
    for (int k = 0; k < 64; k++) {
        float a[4];
        #pragma unroll
        for (int i = 0; i < 4; i++) a[i] = Xs[(ty * 4 + i) * 68 + k];
        const float4 b0 = *(const float4*)&Ws[k * 256 + tx * 16 + 0];
        const float4 b1 = *(const float4*)&Ws[k * 256 + tx * 16 + 4];
        const float4 b2 = *(const float4*)&Ws[k * 256 + tx * 16 + 8];
        const float4 b3 = *(const float4*)&Ws[k * 256 + tx * 16 + 12];
        float b[16] = {b0.x, b0.y, b0.z, b0.w, b1.x, b1.y, b1.z, b1.w,
                       b2.x, b2.y, b2.z, b2.w, b3.x, b3.y, b3.z, b3.w};
        #pragma unroll
        for (int i = 0; i < 4; i++)
            #pragma unroll
            for (int j = 0; j < 16; j++)
                acc[i][j] = fmaf(a[i], b[j], acc[i][j]);
    }

    float* dst = (tx < 8) ? g_PR : g_PC;
    int    cb  = (tx < 8) ? tx * 16 : (tx - 8) * 16;
    #pragma unroll
    for (int i = 0; i < 4; i++) {
        int n = n0 + ty * 4 + i;
        if (n >= NN) continue;
        #pragma unroll
        for (int j = 0; j < 16; j += 4) {
            float4 o = make_float4(acc[i][j], acc[i][j + 1],
                                   acc[i][j + 2], acc[i][j + 3]);
            *(float4*)&dst[n * 128 + cb + j] = o;
        }
    }
}

// ---------------------------------------------------------------------------
// Edge kernel — tf32 mma.sync (sm_80-class PTX, tensor pipe).
// 128 edges/block, 8 warps; warp w owns rows [16w, 16w+16).
//
// SMEM (floats):
//   [0,      8192)  A1frag  [w][kk][lane][4]   (fragment-ordered edge_attr)
//   [8192,  16384)  B1frag  [kk][nn][lane][2]  (fragment-ordered W1a^T)
//   [0,     16896)  H       [128][132]         (overlay; live after sync)
//   [16896, 25088)  B2frag  [kk][nn][lane][2]  (fragment-ordered W2^T)
// total 25088 floats = 100352 B  -> 2 CTAs/SM
// ---------------------------------------------------------------------------
constexpr int F_A1 = 0;
constexpr int F_B1 = 8192;
constexpr int F_B2 = 16896;
constexpr int EDGE_SMEM_BYTES = (16896 + 8192) * 4;   // 100352

__global__ void __launch_bounds__(256, 2) edge_kernel(
    const float* __restrict__ edge_attr,
    const int*   __restrict__ edge_index,   // [2][NE]
    const float* __restrict__ eW1,
    const float* __restrict__ eb1,
    const float* __restrict__ eW2,
    const float* __restrict__ eb2,
    float* __restrict__ out_edge)
{
    extern __shared__ float sm[];
    uint32_t* smu = reinterpret_cast<uint32_t*>(sm);
    const int tid  = threadIdx.x;
    const int lane = tid & 31;
    const int w    = tid >> 5;
    const int gr   = lane >> 2;   // group row
    const int ct   = lane & 3;    // thread-in-group
    const int e0   = blockIdx.x * 128;

    // ---- phase 1: fragment-ordered fills (tf32-rounded) ----
    // A1frag: a_i of warp ww, kstep kk: row = 16ww + (ln>>2) + (i&1)*8,
    //                                   col = kk*8 + (ln&3) + (i>>1)*4
    for (int idx = tid; idx < 8192; idx += 256) {
        int i = idx & 3, ln = (idx >> 2) & 31, kk = (idx >> 7) & 7, ww = idx >> 10;
        int row = 16 * ww + (ln >> 2) + (i & 1) * 8;
        int col = kk * 8 + (ln & 3) + (i >> 1) * 4;
        smu[F_A1 + idx] = f32_to_tf32(edge_attr[(size_t)(e0 + row) * 64 + col]);
    }
    // B1frag: b_j at (kk,nn): k = kk*8 + (ln&3) + j*4, n = nn*8 + (ln>>2)
    for (int idx = tid; idx < 8192; idx += 256) {
        int j = idx & 1, ln = (idx >> 1) & 31, nn = (idx >> 6) & 15, kk = idx >> 10;
        int k = kk * 8 + (ln & 3) + j * 4;
        int n = nn * 8 + (ln >> 2);
        smu[F_B1 + idx] = f32_to_tf32(eW1[k * 128 + n]);
    }
    // B2frag: k = kk*8 + (ln&3) + j*4 (K=128), n = nn*8 + (ln>>2) (N=64)
    for (int idx = tid; idx < 8192; idx += 256) {
        int j = idx & 1, ln = (idx >> 1) & 31, nn = (idx >> 6) & 7, kk = idx >> 9;
        int k = kk * 8 + (ln & 3) + j * 4;
        int n = nn * 8 + (ln >> 2);
        smu[F_B2 + idx] = f32_to_tf32(eW2[k * 64 + n]);
    }
    __syncthreads();

    // ---- phase 2: layer-1 mma  C1[16,128] per warp ----
    float acc[16][4];
    #pragma unroll
    for (int nn = 0; nn < 16; nn++) {
        acc[nn][0] = acc[nn][1] = acc[nn][2] = acc[nn][3] = 0.f;
    }
    #pragma unroll
    for (int kk = 0; kk < 8; kk++) {
        uint32_t a[4];
        const uint4 av = *(const uint4*)&smu[F_A1 + (w * 8 + kk) * 128 + lane * 4];
        a[0] = av.x; a[1] = av.y; a[2] = av.z; a[3] = av.w;
        #pragma unroll
        for (int nn = 0; nn < 16; nn++) {
            uint32_t b[2];
            const uint2 bv = *(const uint2*)&smu[F_B1 + (kk * 16 + nn) * 64 + lane * 2];
            b[0] = bv.x; b[1] = bv.y;
            mma_tf32(acc[nn], a, b);
        }
    }
    __syncthreads();   // A1frag/B1frag dead; H overlay becomes writable

    // ---- phase 3: dump raw C1 to H row-major [128][132] ----
    #pragma unroll
    for (int nn = 0; nn < 16; nn++) {
        int col = nn * 8 + 2 * ct;
        *(float2*)&sm[(16 * w + gr) * 132 + col]     = make_float2(acc[nn][0], acc[nn][1]);
        *(float2*)&sm[(16 * w + gr + 8) * 132 + col] = make_float2(acc[nn][2], acc[nn][3]);
    }
    __syncthreads();

    // ---- phase 4: per-row epilogue: H = tf32(relu(H + PR + PC + eb1)) ----
    {
        int r = tid >> 1, h = tid & 1;
        int e  = e0 + r;
        int re = edge_index[e];
        int ce = edge_index[NE + e];
        const float* prp = g_PR + (size_t)re * 128 + h * 64;
        const float* pcp = g_PC + (size_t)ce * 128 + h * 64;
        const float* bbp = eb1 + h * 64;
        float* hp = &sm[r * 132 + h * 64];
        #pragma unroll
        for (int j = 0; j < 16; j++) {
            float4 hv = *(float4*)(hp + j * 4);
            float4 pr = *(const float4*)(prp + j * 4);
            float4 pc = *(const float4*)(pcp + j * 4);
            float4 bb = *(const float4*)(bbp + j * 4);
            uint4 o;
            o.x = f32_to_tf32(fmaxf(hv.x + pr.x + pc.x + bb.x, 0.f));
            o.y = f32_to_tf32(fmaxf(hv.y + pr.y + pc.y + bb.y, 0.f));
            o.z = f32_to_tf32(fmaxf(hv.z + pr.z + pc.z + bb.z, 0.f));
            o.w = f32_to_tf32(fmaxf(hv.w + pr.w + pc.w + bb.w, 0.f));
            *(uint4*)(hp + j * 4) = o;
        }
    }
    __syncthreads();

    // ---- phase 5: layer-2 mma  C2[16,64] per warp (A = H from smem) ----
    float acc2[8][4];
    #pragma unroll
    for (int nn = 0; nn < 8; nn++) {
        acc2[nn][0] = acc2[nn][1] = acc2[nn][2] = acc2[nn][3] = 0.f;
    }
    {
        const int rb = 16 * w + gr;
        #pragma unroll
        for (int kk = 0; kk < 16; kk++) {
            uint32_t a[4];
            a[0] = smu[rb * 132 + kk * 8 + ct];
            a[1] = smu[(rb + 8) * 132 + kk * 8 + ct];
            a[2] = smu[rb * 132 + kk * 8 + ct + 4];
            a[3] = smu[(rb + 8) * 132 + kk * 8 + ct + 4];
            #pragma unroll
            for (int nn = 0; nn < 8; nn++) {
                uint32_t b[2];
                const uint2 bv = *(const uint2*)&smu[F_B2 + (kk * 8 + nn) * 64 + lane * 2];
                b[0] = bv.x; b[1] = bv.y;
                mma_tf32(acc2[nn], a, b);
            }
        }
    }

    // ---- phase 6: epilogue 2: out_edge write + red.v2 scatter ----
    {
        int r1 = 16 * w + gr, r2 = r1 + 8;
        int ce1 = edge_index[NE + e0 + r1];
        int ce2 = edge_index[NE + e0 + r2];
        float* op1 = out_edge + (size_t)(e0 + r1) * 64;
        float* op2 = out_edge + (size_t)(e0 + r2) * 64;
        float* mp1 = g_msg + (size_t)ce1 * 64;
        float* mp2 = g_msg + (size_t)ce2 * 64;
        #pragma unroll
        for (int nn = 0; nn < 8; nn++) {
            int col = nn * 8 + 2 * ct;
            float2 bb = *(const float2*)(eb2 + col);
            float2 o1 = make_float2(acc2[nn][0] + bb.x, acc2[nn][1] + bb.y);
            float2 o2 = make_float2(acc2[nn][2] + bb.x, acc2[nn][3] + bb.y);
            *(float2*)(op1 + col) = o1;
            *(float2*)(op2 + col) = o2;
            asm volatile("red.global.add.v2.f32 [%0], {%1,%2};"
                         :: "l"(mp1 + col), "f"(o1.x), "f"(o1.y) : "memory");
            asm volatile("red.global.add.v2.f32 [%0], {%1,%2};"
                         :: "l"(mp2 + col), "f"(o2.x), "f"(o2.y) : "memory");
        }
    }
}

// ---------------------------------------------------------------------------
// Node kernel (fp32): x_new = relu([x|msg]@nW1 + nb1) @ nW2 + nb2
// ---------------------------------------------------------------------------
__global__ void __launch_bounds__(256, 2) node_kernel(
    const float* __restrict__ x,
    const float* __restrict__ nW1, const float* __restrict__ nb1,
    const float* __restrict__ nW2, const float* __restrict__ nb2,
    float* __restrict__ out_node)
{
    extern __shared__ float sm[];
    float* buf = sm;                      // [64][132]
    float* W1s = buf + 64 * 132;          // [64][128]
    float* W2s = W1s + 64 * 128;          // [128][64]

    const int n0  = blockIdx.x * 64;
    const int tid = threadIdx.x;

    for (int idx = tid; idx < 64 * 128; idx += 256) {
        int r = idx >> 7, c = idx & 127;
        int n = n0 + r;
        float v = 0.f;
        if (n < NN) v = (c < 64) ? x[n * 64 + c] : g_msg[n * 64 + (c - 64)];
        buf[r * 132 + c] = v;
    }
    for (int idx = tid; idx < 128 * 64; idx += 256) W2s[idx] = nW2[idx];

    const int tx = tid & 15;
    const int ty = tid >> 4;

    float acc[4][8];
    #pragma unroll
    for (int i = 0; i < 4; i++)
        #pragma unroll
        for (int j = 0; j < 8; j++) acc[i][j] = 0.f;

    #pragma unroll
    for (int half = 0; half < 2; half++) {
        for (int idx = tid; idx < 64 * 128; idx += 256)
            W1s[idx] = nW1[half * 64 * 128 + idx];
        __syncthreads();

        #pragma unroll 4
        for (int k = 0; k < 64; k++) {
            float a[4];
            #pragma unroll
            for (int i = 0; i < 4; i++)
                a[i] = buf[(ty * 4 + i) * 132 + half * 64 + k];
            const float4 b0 = *(const float4*)&W1s[k * 128 + tx * 8 + 0];
            const float4 b1 = *(const float4*)&W1s[k * 128 + tx * 8 + 4];
            float b[8] = {b0.x, b0.y, b0.z, b0.w, b1.x, b1.y, b1.z, b1.w};
            #pragma unroll
            for (int i = 0; i < 4; i++)
                #pragma unroll
                for (int j = 0; j < 8; j++)
                    acc[i][j] = fmaf(a[i], b[j], acc[i][j]);
        }
        __syncthreads();
    }

    const float4 n1a = *(const float4*)&nb1[tx * 8 + 0];
    const float4 n1b = *(const float4*)&nb1[tx * 8 + 4];
    float bias1[8] = {n1a.x, n1a.y, n1a.z, n1a.w, n1b.x, n1b.y, n1b.z, n1b.w};
    #pragma unroll
    for (int i = 0; i < 4; i++) {
        float h[8];
        #pragma unroll
        for (int j = 0; j < 8; j++) {
            float v = acc[i][j] + bias1[j];
            h[j] = v > 0.f ? v : 0.f;
        }
        float* hp = &buf[(ty * 4 + i) * 132 + tx * 8];
        *(float4*)(hp + 0) = make_float4(h[0], h[1], h[2], h[3]);
        *(float4*)(hp + 4) = make_float4(h[4], h[5], h[6], h[7]);
    }
    __syncthreads();

    float acc2[4][4];
    #pragma unroll
    for (int i = 0; i < 4; i++)
        #pragma unroll
        for (int j = 0; j < 4; j++) acc2[i][j] = 0.f;

    #pragma unroll 4
    for (int k = 0; k < 128; k++) {
        float a[4];
        #pragma unroll
        for (int i = 0; i < 4; i++) a[i] = buf[(ty * 4 + i) * 132 + k];
        const float4 b = *(const float4*)&W2s[k * 64 + tx * 4];
        #pragma unroll
        for (int i = 0; i < 4; i++) {
            acc2[i][0] = fmaf(a[i], b.x, acc2[i][0]);
            acc2[i][1] = fmaf(a[i], b.y, acc2[i][1]);
            acc2[i][2] = fmaf(a[i], b.z, acc2[i][2]);
            acc2[i][3] = fmaf(a[i], b.w, acc2[i][3]);
        }
    }

    const float4 b2 = *(const float4*)&nb2[tx * 4];
    #pragma unroll
    for (int i = 0; i < 4; i++) {
        int n = n0 + ty * 4 + i;
        if (n >= NN) continue;
        float4 o = make_float4(acc2[i][0] + b2.x, acc2[i][1] + b2.y,
                               acc2[i][2] + b2.z, acc2[i][3] + b2.w);
        *(float4*)&out_node[n * 64 + tx * 4] = o;
    }
}

// ---------------------------------------------------------------------------
extern "C" void kernel_launch(void* const* d_in, const int* in_sizes, int n_in,
                              void* d_out, int out_size)
{
    const float* x    = (const float*)d_in[0];
    const int*   ei   = (const int*)  d_in[1];
    const float* ea   = (const float*)d_in[2];
    const float* eW1  = (const float*)d_in[3];
    const float* eb1  = (const float*)d_in[4];
    const float* eW2  = (const float*)d_in[5];
    const float* eb2  = (const float*)d_in[6];
    const float* nW1  = (const float*)d_in[7];
    const float* nb1  = (const float*)d_in[8];
    const float* nW2  = (const float*)d_in[9];
    const float* nb2  = (const float*)d_in[10];

    float* out_node = (float*)d_out;             // [NN, 64]
    float* out_edge = (float*)d_out + NN * ND;   // [NE, 64]

    const int smem_pre  = (64 * 68 + 64 * 256) * 4;             // 82944
    const int smem_node = (64 * 132 + 64 * 128 + 128 * 64) * 4; // 99328

    cudaFuncSetAttribute(precompute_kernel,
        cudaFuncAttributeMaxDynamicSharedMemorySize, smem_pre);
    cudaFuncSetAttribute(edge_kernel,
        cudaFuncAttributeMaxDynamicSharedMemorySize, EDGE_SMEM_BYTES);
    cudaFuncSetAttribute(node_kernel,
        cudaFuncAttributeMaxDynamicSharedMemorySize, smem_node);

    zero_msg_kernel<<<(NN * ED / 4) / 256, 256>>>();
    precompute_kernel<<<(NN + 63) / 64, 256, smem_pre>>>(x, eW1);
    edge_kernel<<<NE / 128, 256, EDGE_SMEM_BYTES>>>(ea, ei, eW1, eb1, eW2, eb2, out_edge);
    node_kernel<<<(NN + 63) / 64, 256, smem_node>>>(x, nW1, nb1, nW2, nb2, out_node);
}

// round 7
// speedup vs baseline: 2.1171x; 1.0391x over previous
#include <cuda_runtime.h>
#include <cstdint>

// Problem constants
constexpr int NN  = 50000;   // nodes
constexpr int NE  = 800000;  // edges
constexpr int ND  = 64;      // node dim
constexpr int ED  = 64;      // edge dim
constexpr int HID = 128;     // hidden

// Scratch (device globals: allocation-free)
__device__ float g_PR[NN * HID];   // x @ eW1[64:128]   (source-node term, fp32 exact)
__device__ float g_PC[NN * HID];   // x @ eW1[128:192]  (dest-node term, fp32 exact)
__device__ float g_msg[NN * ED];   // scatter-add accumulator

// ---------------------------------------------------------------------------
// helpers
// ---------------------------------------------------------------------------
__device__ __forceinline__ uint32_t f32_to_tf32(float f) {
    uint32_t u;
    asm("cvt.rna.tf32.f32 %0, %1;" : "=r"(u) : "f"(f));
    return u;
}

// D += A@B  (m16n8k8 tf32, row.col), D/C in-place
__device__ __forceinline__ void mma_tf32(float d[4], const uint32_t a[4],
                                         const uint32_t b[2]) {
    asm volatile(
        "mma.sync.aligned.m16n8k8.row.col.f32.tf32.tf32.f32 "
        "{%0,%1,%2,%3}, {%4,%5,%6,%7}, {%8,%9}, {%0,%1,%2,%3};"
        : "+f"(d[0]), "+f"(d[1]), "+f"(d[2]), "+f"(d[3])
        : "r"(a[0]), "r"(a[1]), "r"(a[2]), "r"(a[3]), "r"(b[0]), "r"(b[1]));
}

// ---------------------------------------------------------------------------
// Zero the message accumulator
// ---------------------------------------------------------------------------
__global__ void zero_msg_kernel() {
    int i = blockIdx.x * blockDim.x + threadIdx.x;
    reinterpret_cast<float4*>(g_msg)[i] = make_float4(0.f, 0.f, 0.f, 0.f);
}

// ---------------------------------------------------------------------------
// Precompute PR/PC (fp32 exact): GEMM [NN,64] @ [64,256]
// ---------------------------------------------------------------------------
__global__ void __launch_bounds__(256, 2) precompute_kernel(
    const float* __restrict__ x, const float* __restrict__ eW1)
{
    extern __shared__ float sm[];
    float* Xs = sm;               // [64][68]
    float* Ws = sm + 64 * 68;     // [64][256]

    const int n0 = blockIdx.x * 64;
    const int tid = threadIdx.x;

    for (int idx = tid; idx < 64 * 64; idx += 256) {
        int r = idx >> 6, c = idx & 63;
        int n = n0 + r;
        Xs[r * 68 + c] = (n < NN) ? x[n * 64 + c] : 0.f;
    }
    for (int idx = tid; idx < 64 * 256; idx += 256) {
        int k = idx >> 8, j = idx & 255;
        float v = (j < 128) ? eW1[(64 + k) * 128 + j]
                            : eW1[(128 + k) * 128 + (j - 128)];
        Ws[k * 256 + j] = v;
    }
    __syncthreads();

    const int tx = tid & 15;
    const int ty = tid >> 4;

    float acc[4][16];
    #pragma unroll
    for (int i = 0; i < 4; i++)
        #pragma unroll
        for (int j = 0; j < 16; j++) acc[i][j] = 0.f;

    #pragma unroll 4
    for (int k = 0; k < 64; k++) {
        float a[4];
        #pragma unroll
        for (int i = 0; i < 4; i++) a[i] = Xs[(ty * 4 + i) * 68 + k];
        const float4 b0 = *(const float4*)&Ws[k * 256 + tx * 16 + 0];
        const float4 b1 = *(const float4*)&Ws[k * 256 + tx * 16 + 4];
        const float4 b2 = *(const float4*)&Ws[k * 256 + tx * 16 + 8];
        const float4 b3 = *(const float4*)&Ws[k * 256 + tx * 16 + 12];
        float b[16] = {b0.x, b0.y, b0.z, b0.w, b1.x, b1.y, b1.z, b1.w,
                       b2.x, b2.y, b2.z, b2.w, b3.x, b3.y, b3.z, b3.w};
        #pragma unroll
        for (int i = 0; i < 4; i++)
            #pragma unroll
            for (int j = 0; j < 16; j++)
                acc[i][j] = fmaf(a[i], b[j], acc[i][j]);
    }

    float* dst = (tx < 8) ? g_PR : g_PC;
    int    cb  = (tx < 8) ? tx * 16 : (tx - 8) * 16;
    #pragma unroll
    for (int i = 0; i < 4; i++) {
        int n = n0 + ty * 4 + i;
        if (n >= NN) continue;
        #pragma unroll
        for (int j = 0; j < 16; j += 4) {
            float4 o = make_float4(acc[i][j], acc[i][j + 1],
                                   acc[i][j + 2], acc[i][j + 3]);
            *(float4*)&dst[n * 128 + cb + j] = o;
        }
    }
}

// ---------------------------------------------------------------------------
// Edge kernel — tf32 mma.sync, coalesced gmem paths.
// 128 edges/block, 8 warps; warp w owns rows [16w, 16w+16).
//
// SMEM (floats):
//   [0,      8448)  A1frag  [slab=ww*8+kk][132]  (lane*4+i within slab)
//   [8448,  16896)  B1frag  [pane=kk*16+nn][66]  (lane*2+j within pane)
//   [0,     16896)  H       [128][132]           (overlay after L1)
//   [0,      8704)  C2s     [128][68]            (overlay after L2)
//   [16896, 25344)  B2frag  [pane=kk*8+nn][66]
//   [25344, 25472)  ce      [128] ints
// total 25472 floats = 101888 B  -> 2 CTAs/SM
// ---------------------------------------------------------------------------
constexpr int F_A1 = 0;
constexpr int F_B1 = 8448;
constexpr int F_B2 = 16896;
constexpr int F_CE = 25344;
constexpr int EDGE_SMEM_BYTES = 25472 * 4;   // 101888

__global__ void __launch_bounds__(256, 2) edge_kernel(
    const float* __restrict__ edge_attr,
    const int*   __restrict__ edge_index,   // [2][NE]
    const float* __restrict__ eW1,
    const float* __restrict__ eb1,
    const float* __restrict__ eW2,
    const float* __restrict__ eb2,
    float* __restrict__ out_edge)
{
    extern __shared__ float sm[];
    uint32_t* smu = reinterpret_cast<uint32_t*>(sm);
    const int tid  = threadIdx.x;
    const int lane = tid & 31;
    const int w    = tid >> 5;
    const int gr   = lane >> 2;   // group row
    const int ct   = lane & 3;    // thread-in-group
    const int e0   = blockIdx.x * 128;

    // ---- phase 1: coalesced LDG.128, fragment-scattered STS ----
    // A1: edge_attr [128 rows][64 cols]; frag (ww,kk,ln,i):
    //     row = 16ww + (ln>>2) + (i&1)*8, col = kk*8 + (ln&3) + (i>>1)*4
    for (int t = tid; t < 2048; t += 256) {
        int row = t >> 4, c4 = (t & 15) << 2;
        float4 v = *(const float4*)&edge_attr[(size_t)(e0 + row) * 64 + c4];
        int slab = (row >> 4) * 8 + (c4 >> 3);
        int i    = ((row >> 3) & 1) | (((c4 >> 2) & 1) << 1);
        int ln0  = (row & 7) << 2;
        uint32_t* p = &smu[F_A1 + slab * 132 + i];
        p[(ln0 + 0) * 4] = f32_to_tf32(v.x);
        p[(ln0 + 1) * 4] = f32_to_tf32(v.y);
        p[(ln0 + 2) * 4] = f32_to_tf32(v.z);
        p[(ln0 + 3) * 4] = f32_to_tf32(v.w);
    }
    // B1: eW1 rows 0..63 [64][128]; frag (kk,nn,ln,j):
    //     k = kk*8 + (ln&3) + 4j, n = nn*8 + (ln>>2)
    for (int t = tid; t < 2048; t += 256) {
        int k = t >> 5, n4 = (t & 31) << 2;
        float4 v = *(const float4*)&eW1[k * 128 + n4];
        int pane = (k >> 3) * 16 + (n4 >> 3);
        int j    = (k >> 2) & 1;
        int ln0  = ((n4 & 7) << 2) | (k & 3);
        uint32_t* p = &smu[F_B1 + pane * 66 + j];
        p[(ln0 + 0)  * 2] = f32_to_tf32(v.x);
        p[(ln0 + 4)  * 2] = f32_to_tf32(v.y);
        p[(ln0 + 8)  * 2] = f32_to_tf32(v.z);
        p[(ln0 + 12) * 2] = f32_to_tf32(v.w);
    }
    // B2: eW2 [128][64]
    for (int t = tid; t < 2048; t += 256) {
        int k = t >> 4, n4 = (t & 15) << 2;
        float4 v = *(const float4*)&eW2[k * 64 + n4];
        int pane = (k >> 3) * 8 + (n4 >> 3);
        int j    = (k >> 2) & 1;
        int ln0  = ((n4 & 7) << 2) | (k & 3);
        uint32_t* p = &smu[F_B2 + pane * 66 + j];
        p[(ln0 + 0)  * 2] = f32_to_tf32(v.x);
        p[(ln0 + 4)  * 2] = f32_to_tf32(v.y);
        p[(ln0 + 8)  * 2] = f32_to_tf32(v.z);
        p[(ln0 + 12) * 2] = f32_to_tf32(v.w);
    }
    __syncthreads();

    // ---- phase 2: layer-1 mma  C1[16,128] per warp ----
    float acc[16][4];
    #pragma unroll
    for (int nn = 0; nn < 16; nn++) {
        acc[nn][0] = acc[nn][1] = acc[nn][2] = acc[nn][3] = 0.f;
    }
    #pragma unroll
    for (int kk = 0; kk < 8; kk++) {
        uint32_t a[4];
        const uint4 av = *(const uint4*)&smu[F_A1 + (w * 8 + kk) * 132 + lane * 4];
        a[0] = av.x; a[1] = av.y; a[2] = av.z; a[3] = av.w;
        #pragma unroll
        for (int nn = 0; nn < 16; nn++) {
            uint32_t b[2];
            const uint2 bv = *(const uint2*)&smu[F_B1 + (kk * 16 + nn) * 66 + lane * 2];
            b[0] = bv.x; b[1] = bv.y;
            mma_tf32(acc[nn], a, b);
        }
    }
    __syncthreads();   // A1frag/B1frag dead; H overlay becomes writable

    // ---- phase 3: dump raw C1 to H row-major [128][132] ----
    #pragma unroll
    for (int nn = 0; nn < 16; nn++) {
        int col = nn * 8 + 2 * ct;
        *(float2*)&sm[(16 * w + gr) * 132 + col]     = make_float2(acc[nn][0], acc[nn][1]);
        *(float2*)&sm[(16 * w + gr + 8) * 132 + col] = make_float2(acc[nn][2], acc[nn][3]);
    }
    __syncthreads();

    // ---- phase 4: per-row epilogue: H = tf32(relu(H + PR + PC + eb1)) ----
    {
        int r = tid >> 1, h = tid & 1;
        int e  = e0 + r;
        int re = edge_index[e];
        int ce = edge_index[NE + e];
        if (h == 0) ((int*)&smu[F_CE])[r] = ce;
        const float* prp = g_PR + (size_t)re * 128 + h * 64;
        const float* pcp = g_PC + (size_t)ce * 128 + h * 64;
        const float* bbp = eb1 + h * 64;
        float* hp = &sm[r * 132 + h * 64];
        #pragma unroll
        for (int j = 0; j < 16; j++) {
            float4 hv = *(float4*)(hp + j * 4);
            float4 pr = *(const float4*)(prp + j * 4);
            float4 pc = *(const float4*)(pcp + j * 4);
            float4 bb = *(const float4*)(bbp + j * 4);
            uint4 o;
            o.x = f32_to_tf32(fmaxf(hv.x + pr.x + pc.x + bb.x, 0.f));
            o.y = f32_to_tf32(fmaxf(hv.y + pr.y + pc.y + bb.y, 0.f));
            o.z = f32_to_tf32(fmaxf(hv.z + pr.z + pc.z + bb.z, 0.f));
            o.w = f32_to_tf32(fmaxf(hv.w + pr.w + pc.w + bb.w, 0.f));
            *(uint4*)(hp + j * 4) = o;
        }
    }
    __syncthreads();

    // ---- phase 5: layer-2 mma  C2[16,64] per warp (A = H from smem) ----
    float acc2[8][4];
    #pragma unroll
    for (int nn = 0; nn < 8; nn++) {
        acc2[nn][0] = acc2[nn][1] = acc2[nn][2] = acc2[nn][3] = 0.f;
    }
    {
        const int rb = 16 * w + gr;
        #pragma unroll
        for (int kk = 0; kk < 16; kk++) {
            uint32_t a[4];
            a[0] = smu[rb * 132 + kk * 8 + ct];
            a[1] = smu[(rb + 8) * 132 + kk * 8 + ct];
            a[2] = smu[rb * 132 + kk * 8 + ct + 4];
            a[3] = smu[(rb + 8) * 132 + kk * 8 + ct + 4];
            #pragma unroll
            for (int nn = 0; nn < 8; nn++) {
                uint32_t b[2];
                const uint2 bv = *(const uint2*)&smu[F_B2 + (kk * 8 + nn) * 66 + lane * 2];
                b[0] = bv.x; b[1] = bv.y;
                mma_tf32(acc2[nn], a, b);
            }
        }
    }
    __syncthreads();   // H dead; C2s overlay becomes writable

    // ---- phase 6: dump C2 to C2s[128][68] ----
    #pragma unroll
    for (int nn = 0; nn < 8; nn++) {
        int col = nn * 8 + 2 * ct;
        *(float2*)&sm[(16 * w + gr) * 68 + col]     = make_float2(acc2[nn][0], acc2[nn][1]);
        *(float2*)&sm[(16 * w + gr + 8) * 68 + col] = make_float2(acc2[nn][2], acc2[nn][3]);
    }
    __syncthreads();

    // ---- phase 7: coalesced out_edge write + red.v4 scatter ----
    {
        int sub  = tid >> 4;             // 0..15
        int col4 = (tid & 15) << 2;
        float4 bb = *(const float4*)(eb2 + col4);
        const int* cep = (const int*)&smu[F_CE];
        #pragma unroll
        for (int p = 0; p < 8; p++) {
            int row = p * 16 + sub;
            float4 c = *(float4*)&sm[row * 68 + col4];
            float4 o = make_float4(c.x + bb.x, c.y + bb.y, c.z + bb.z, c.w + bb.w);
            *(float4*)&out_edge[(size_t)(e0 + row) * 64 + col4] = o;
            float* mp = g_msg + (size_t)cep[row] * 64 + col4;
            asm volatile("red.global.add.v4.f32 [%0], {%1,%2,%3,%4};"
                         :: "l"(mp), "f"(o.x), "f"(o.y), "f"(o.z), "f"(o.w)
                         : "memory");
        }
    }
}

// ---------------------------------------------------------------------------
// Node kernel (fp32): x_new = relu([x|msg]@nW1 + nb1) @ nW2 + nb2
// ---------------------------------------------------------------------------
__global__ void __launch_bounds__(256, 2) node_kernel(
    const float* __restrict__ x,
    const float* __restrict__ nW1, const float* __restrict__ nb1,
    const float* __restrict__ nW2, const float* __restrict__ nb2,
    float* __restrict__ out_node)
{
    extern __shared__ float sm[];
    float* buf = sm;                      // [64][132]
    float* W1s = buf + 64 * 132;          // [64][128]
    float* W2s = W1s + 64 * 128;          // [128][64]

    const int n0  = blockIdx.x * 64;
    const int tid = threadIdx.x;

    for (int idx = tid; idx < 64 * 128; idx += 256) {
        int r = idx >> 7, c = idx & 127;
        int n = n0 + r;
        float v = 0.f;
        if (n < NN) v = (c < 64) ? x[n * 64 + c] : g_msg[n * 64 + (c - 64)];
        buf[r * 132 + c] = v;
    }
    for (int idx = tid; idx < 128 * 64; idx += 256) W2s[idx] = nW2[idx];

    const int tx = tid & 15;
    const int ty = tid >> 4;

    float acc[4][8];
    #pragma unroll
    for (int i = 0; i < 4; i++)
        #pragma unroll
        for (int j = 0; j < 8; j++) acc[i][j] = 0.f;

    #pragma unroll
    for (int half = 0; half < 2; half++) {
        for (int idx = tid; idx < 64 * 128; idx += 256)
            W1s[idx] = nW1[half * 64 * 128 + idx];
        __syncthreads();

        #pragma unroll 4
        for (int k = 0; k < 64; k++) {
            float a[4];
            #pragma unroll
            for (int i = 0; i < 4; i++)
                a[i] = buf[(ty * 4 + i) * 132 + half * 64 + k];
            const float4 b0 = *(const float4*)&W1s[k * 128 + tx * 8 + 0];
            const float4 b1 = *(const float4*)&W1s[k * 128 + tx * 8 + 4];
            float b[8] = {b0.x, b0.y, b0.z, b0.w, b1.x, b1.y, b1.z, b1.w};
            #pragma unroll
            for (int i = 0; i < 4; i++)
                #pragma unroll
                for (int j = 0; j < 8; j++)
                    acc[i][j] = fmaf(a[i], b[j], acc[i][j]);
        }
        __syncthreads();
    }

    const float4 n1a = *(const float4*)&nb1[tx * 8 + 0];
    const float4 n1b = *(const float4*)&nb1[tx * 8 + 4];
    float bias1[8] = {n1a.x, n1a.y, n1a.z, n1a.w, n1b.x, n1b.y, n1b.z, n1b.w};
    #pragma unroll
    for (int i = 0; i < 4; i++) {
        float h[8];
        #pragma unroll
        for (int j = 0; j < 8; j++) {
            float v = acc[i][j] + bias1[j];
            h[j] = v > 0.f ? v : 0.f;
        }
        float* hp = &buf[(ty * 4 + i) * 132 + tx * 8];
        *(float4*)(hp + 0) = make_float4(h[0], h[1], h[2], h[3]);
        *(float4*)(hp + 4) = make_float4(h[4], h[5], h[6], h[7]);
    }
    __syncthreads();

    float acc2[4][4];
    #pragma unroll
    for (int i = 0; i < 4; i++)
        #pragma unroll
        for (int j = 0; j < 4; j++) acc2[i][j] = 0.f;

    #pragma unroll 4
    for (int k = 0; k < 128; k++) {
        float a[4];
        #pragma unroll
        for (int i = 0; i < 4; i++) a[i] = buf[(ty * 4 + i) * 132 + k];
        const float4 b = *(const float4*)&W2s[k * 64 + tx * 4];
        #pragma unroll
        for (int i = 0; i < 4; i++) {
            acc2[i][0] = fmaf(a[i], b.x, acc2[i][0]);
            acc2[i][1] = fmaf(a[i], b.y, acc2[i][1]);
            acc2[i][2] = fmaf(a[i], b.z, acc2[i][2]);
            acc2[i][3] = fmaf(a[i], b.w, acc2[i][3]);
        }
    }

    const float4 b2 = *(const float4*)&nb2[tx * 4];
    #pragma unroll
    for (int i = 0; i < 4; i++) {
        int n = n0 + ty * 4 + i;
        if (n >= NN) continue;
        float4 o = make_float4(acc2[i][0] + b2.x, acc2[i][1] + b2.y,
                               acc2[i][2] + b2.z, acc2[i][3] + b2.w);
        *(float4*)&out_node[n * 64 + tx * 4] = o;
    }
}

// ---------------------------------------------------------------------------
extern "C" void kernel_launch(void* const* d_in, const int* in_sizes, int n_in,
                              void* d_out, int out_size)
{
    const float* x    = (const float*)d_in[0];
    const int*   ei   = (const int*)  d_in[1];
    const float* ea   = (const float*)d_in[2];
    const float* eW1  = (const float*)d_in[3];
    const float* eb1  = (const float*)d_in[4];
    const float* eW2  = (const float*)d_in[5];
    const float* eb2  = (const float*)d_in[6];
    const float* nW1  = (const float*)d_in[7];
    const float* nb1  = (const float*)d_in[8];
    const float* nW2  = (const float*)d_in[9];
    const float* nb2  = (const float*)d_in[10];

    float* out_node = (float*)d_out;             // [NN, 64]
    float* out_edge = (float*)d_out + NN * ND;   // [NE, 64]

    const int smem_pre  = (64 * 68 + 64 * 256) * 4;             // 82944
    const int smem_node = (64 * 132 + 64 * 128 + 128 * 64) * 4; // 99328

    cudaFuncSetAttribute(precompute_kernel,
        cudaFuncAttributeMaxDynamicSharedMemorySize, smem_pre);
    cudaFuncSetAttribute(edge_kernel,
        cudaFuncAttributeMaxDynamicSharedMemorySize, EDGE_SMEM_BYTES);
    cudaFuncSetAttribute(node_kernel,
        cudaFuncAttributeMaxDynamicSharedMemorySize, smem_node);

    zero_msg_kernel<<<(NN * ED / 4) / 256, 256>>>();
    precompute_kernel<<<(NN + 63) / 64, 256, smem_pre>>>(x, eW1);
    edge_kernel<<<NE / 128, 256, EDGE_SMEM_BYTES>>>(ea, ei, eW1, eb1, eW2, eb2, out_edge);
    node_kernel<<<(NN + 63) / 64, 256, smem_node>>>(x, nW1, nb1, nW2, nb2, out_node);
}

// round 8
// speedup vs baseline: 3.4011x; 1.6065x over previous
#include <cuda_runtime.h>
#include <cstdint>

// Problem constants
constexpr int NN  = 50000;   // nodes
constexpr int NE  = 800000;  // edges
constexpr int ND  = 64;      // node dim
constexpr int ED  = 64;      // edge dim
constexpr int HID = 128;     // hidden

constexpr int NTILES    = NE / 128;  // 6250
constexpr int EDGE_GRID = 296;       // 2 CTAs x 148 SMs, persistent

// Scratch (device globals: allocation-free)
__device__ float g_PR[NN * HID];   // x @ eW1[64:128]   (source-node term, fp32 exact)
__device__ float g_PC[NN * HID];   // x @ eW1[128:192]  (dest-node term, fp32 exact)
__device__ float g_msg[NN * ED];   // scatter-add accumulator

// ---------------------------------------------------------------------------
// helpers
// ---------------------------------------------------------------------------
__device__ __forceinline__ uint32_t f32_to_tf32(float f) {
    uint32_t u;
    asm("cvt.rna.tf32.f32 %0, %1;" : "=r"(u) : "f"(f));
    return u;
}

// D += A@B  (m16n8k8 tf32, row.col), D/C in-place
__device__ __forceinline__ void mma_tf32(float d[4], const uint32_t a[4],
                                         const uint32_t b[2]) {
    asm volatile(
        "mma.sync.aligned.m16n8k8.row.col.f32.tf32.tf32.f32 "
        "{%0,%1,%2,%3}, {%4,%5,%6,%7}, {%8,%9}, {%0,%1,%2,%3};"
        : "+f"(d[0]), "+f"(d[1]), "+f"(d[2]), "+f"(d[3])
        : "r"(a[0]), "r"(a[1]), "r"(a[2]), "r"(a[3]), "r"(b[0]), "r"(b[1]));
}

__device__ __forceinline__ uint32_t smem_u32(const void* p) {
    uint32_t a;
    asm("{ .reg .u64 t; cvta.to.shared.u64 t, %1; cvt.u32.u64 %0, t; }"
        : "=r"(a) : "l"(p));
    return a;
}

#define CP_ASYNC16(dst_u32, src_ptr) \
    asm volatile("cp.async.cg.shared.global [%0], [%1], 16;" \
                 :: "r"(dst_u32), "l"(src_ptr))
#define CP_COMMIT()  asm volatile("cp.async.commit_group;")
#define CP_WAIT0()   asm volatile("cp.async.wait_group 0;" ::: "memory")

// ---------------------------------------------------------------------------
// Zero the message accumulator
// ---------------------------------------------------------------------------
__global__ void zero_msg_kernel() {
    int i = blockIdx.x * blockDim.x + threadIdx.x;
    reinterpret_cast<float4*>(g_msg)[i] = make_float4(0.f, 0.f, 0.f, 0.f);
}

// ---------------------------------------------------------------------------
// Precompute PR/PC (fp32 exact): GEMM [NN,64] @ [64,256]
// ---------------------------------------------------------------------------
__global__ void __launch_bounds__(256, 2) precompute_kernel(
    const float* __restrict__ x, const float* __restrict__ eW1)
{
    extern __shared__ float sm[];
    float* Xs = sm;               // [64][68]
    float* Ws = sm + 64 * 68;     // [64][256]

    const int n0 = blockIdx.x * 64;
    const int tid = threadIdx.x;

    for (int idx = tid; idx < 64 * 64; idx += 256) {
        int r = idx >> 6, c = idx & 63;
        int n = n0 + r;
        Xs[r * 68 + c] = (n < NN) ? x[n * 64 + c] : 0.f;
    }
    for (int idx = tid; idx < 64 * 256; idx += 256) {
        int k = idx >> 8, j = idx & 255;
        float v = (j < 128) ? eW1[(64 + k) * 128 + j]
                            : eW1[(128 + k) * 128 + (j - 128)];
        Ws[k * 256 + j] = v;
    }
    __syncthreads();

    const int tx = tid & 15;
    const int ty = tid >> 4;

    float acc[4][16];
    #pragma unroll
    for (int i = 0; i < 4; i++)
        #pragma unroll
        for (int j = 0; j < 16; j++) acc[i][j] = 0.f;

    #pragma unroll 4
    for (int k = 0; k < 64; k++) {
        float a[4];
        #pragma unroll
        for (int i = 0; i < 4; i++) a[i] = Xs[(ty * 4 + i) * 68 + k];
        const float4 b0 = *(const float4*)&Ws[k * 256 + tx * 16 + 0];
        const float4 b1 = *(const float4*)&Ws[k * 256 + tx * 16 + 4];
        const float4 b2 = *(const float4*)&Ws[k * 256 + tx * 16 + 8];
        const float4 b3 = *(const float4*)&Ws[k * 256 + tx * 16 + 12];
        float b[16] = {b0.x, b0.y, b0.z, b0.w, b1.x, b1.y, b1.z, b1.w,
                       b2.x, b2.y, b2.z, b2.w, b3.x, b3.y, b3.z, b3.w};
        #pragma unroll
        for (int i = 0; i < 4; i++)
            #pragma unroll
            for (int j = 0; j < 16; j++)
                acc[i][j] = fmaf(a[i], b[j], acc[i][j]);
    }

    float* dst = (tx < 8) ? g_PR : g_PC;
    int    cb  = (tx < 8) ? tx * 16 : (tx - 8) * 16;
    #pragma unroll
    for (int i = 0; i < 4; i++) {
        int n = n0 + ty * 4 + i;
        if (n >= NN) continue;
        #pragma unroll
        for (int j = 0; j < 16; j += 4) {
            float4 o = make_float4(acc[i][j], acc[i][j + 1],
                                   acc[i][j + 2], acc[i][j + 3]);
            *(float4*)&dst[n * 128 + cb + j] = o;
        }
    }
}

// ---------------------------------------------------------------------------
// Edge kernel — persistent, tf32 mma.sync, cp.async A prefetch, register-H.
// 296 CTAs x 256 threads; each CTA loops over tiles of 128 edges.
// Warp w owns rows [16w, 16w+16) of the tile.
//
// SMEM (floats):
//   [0,      8704)  A      [128][68]  row-major, cp.async filled (raw fp32)
//   [8704,  17152)  B1frag [pane=kk*16+nn][66]  (tf32-rna W1a^T fragments)
//   [17152, 25600)  B2frag [pane=kk*8+nn][66]   (tf32-rna W2^T fragments)
//   [25600, 25728)  eb1
//   [25728, 25792)  eb2
// total 25792 floats = 103168 B -> 2 CTAs/SM
// ---------------------------------------------------------------------------
constexpr int S_A   = 0;
constexpr int S_B1  = 8704;
constexpr int S_B2  = 17152;
constexpr int S_EB1 = 25600;
constexpr int S_EB2 = 25728;
constexpr int EDGE_SMEM_BYTES = 25792 * 4;   // 103168

__global__ void __launch_bounds__(256, 2) edge_kernel(
    const float* __restrict__ edge_attr,
    const int*   __restrict__ edge_index,   // [2][NE]
    const float* __restrict__ eW1,
    const float* __restrict__ eb1,
    const float* __restrict__ eW2,
    const float* __restrict__ eb2,
    float* __restrict__ out_edge)
{
    extern __shared__ float sm[];
    uint32_t* smu = reinterpret_cast<uint32_t*>(sm);
    const uint32_t sbase = smem_u32(sm);

    const int tid  = threadIdx.x;
    const int lane = tid & 31;
    const int w    = tid >> 5;
    const int gr   = lane >> 2;   // group row
    const int ct   = lane & 3;    // thread-in-group
    const int s0   = ct >> 1;           // quad shuffle sources
    const int s1   = 2 + (ct >> 1);
    const int sel  = ct & 1;
    const int r1   = 16 * w + gr;       // local tile rows owned
    const int r2   = r1 + 8;

    int tile = blockIdx.x;

    // ---- prologue: cp.async A(tile0); fill B1/B2 fragments + biases once ----
    if (tile < NTILES) {
        int e0 = tile * 128;
        for (int t = tid; t < 2048; t += 256) {
            int row = t >> 4, c4 = (t & 15) << 2;
            CP_ASYNC16(sbase + (S_A + row * 68 + c4) * 4,
                       edge_attr + (size_t)(e0 + row) * 64 + c4);
        }
    }
    CP_COMMIT();

    // B1 = W1a^T fragments: k = kk*8 + (ln&3) + 4j, n = nn*8 + (ln>>2)
    for (int t = tid; t < 2048; t += 256) {
        int k = t >> 5, n4 = (t & 31) << 2;
        float4 v = *(const float4*)&eW1[k * 128 + n4];
        int pane = (k >> 3) * 16 + (n4 >> 3);
        int j    = (k >> 2) & 1;
        int ln0  = ((n4 & 7) << 2) | (k & 3);
        uint32_t* p = &smu[S_B1 + pane * 66 + j];
        p[(ln0 + 0)  * 2] = f32_to_tf32(v.x);
        p[(ln0 + 4)  * 2] = f32_to_tf32(v.y);
        p[(ln0 + 8)  * 2] = f32_to_tf32(v.z);
        p[(ln0 + 12) * 2] = f32_to_tf32(v.w);
    }
    // B2 = W2^T fragments
    for (int t = tid; t < 2048; t += 256) {
        int k = t >> 4, n4 = (t & 15) << 2;
        float4 v = *(const float4*)&eW2[k * 64 + n4];
        int pane = (k >> 3) * 8 + (n4 >> 3);
        int j    = (k >> 2) & 1;
        int ln0  = ((n4 & 7) << 2) | (k & 3);
        uint32_t* p = &smu[S_B2 + pane * 66 + j];
        p[(ln0 + 0)  * 2] = f32_to_tf32(v.x);
        p[(ln0 + 4)  * 2] = f32_to_tf32(v.y);
        p[(ln0 + 8)  * 2] = f32_to_tf32(v.z);
        p[(ln0 + 12) * 2] = f32_to_tf32(v.w);
    }
    if (tid < 128) sm[S_EB1 + tid] = eb1[tid];
    if (tid < 64)  sm[S_EB2 + tid] = eb2[tid];

    CP_WAIT0();
    __syncthreads();

    // ---- persistent tile loop ----
    for (; tile < NTILES; tile += EDGE_GRID) {
        const int e0 = tile * 128;

        // edge indices (issued early; consumed in epilogue)
        const int re1 = edge_index[e0 + r1];
        const int re2 = edge_index[e0 + r2];
        const int ce1 = edge_index[NE + e0 + r1];
        const int ce2 = edge_index[NE + e0 + r2];

        // ---- layer-1 mma: C1[16,128] per warp (A raw-fp32 -> hw tf32) ----
        float acc[16][4];
        #pragma unroll
        for (int nn = 0; nn < 16; nn++) {
            acc[nn][0] = acc[nn][1] = acc[nn][2] = acc[nn][3] = 0.f;
        }
        #pragma unroll
        for (int kk = 0; kk < 8; kk++) {
            uint32_t a[4];
            a[0] = smu[S_A + r1 * 68 + kk * 8 + ct];
            a[1] = smu[S_A + r2 * 68 + kk * 8 + ct];
            a[2] = smu[S_A + r1 * 68 + kk * 8 + ct + 4];
            a[3] = smu[S_A + r2 * 68 + kk * 8 + ct + 4];
            #pragma unroll
            for (int nn = 0; nn < 16; nn++) {
                uint32_t b[2];
                const uint2 bv = *(const uint2*)&smu[S_B1 + (kk * 16 + nn) * 66 + lane * 2];
                b[0] = bv.x; b[1] = bv.y;
                mma_tf32(acc[nn], a, b);
            }
        }
        __syncthreads();   // A consumed; safe to overwrite

        // ---- prefetch next tile's A (latency hidden by epilogue + L2 mma) ----
        {
            int ntile = tile + EDGE_GRID;
            if (ntile < NTILES) {
                int ne0 = ntile * 128;
                for (int t = tid; t < 2048; t += 256) {
                    int row = t >> 4, c4 = (t & 15) << 2;
                    CP_ASYNC16(sbase + (S_A + row * 68 + c4) * 4,
                               edge_attr + (size_t)(ne0 + row) * 64 + c4);
                }
            }
            CP_COMMIT();
        }

        // ---- epilogue in accum layout: H = rna(relu(C1 + PR + PC + eb1)) ----
        {
            const float* PR1 = g_PR + (size_t)re1 * 128;
            const float* PR2 = g_PR + (size_t)re2 * 128;
            const float* PC1 = g_PC + (size_t)ce1 * 128;
            const float* PC2 = g_PC + (size_t)ce2 * 128;
            #pragma unroll
            for (int nn = 0; nn < 16; nn++) {
                int c = nn * 8 + 2 * ct;
                float2 p1 = *(const float2*)&PR1[c];
                float2 q1 = *(const float2*)&PC1[c];
                float2 p2 = *(const float2*)&PR2[c];
                float2 q2 = *(const float2*)&PC2[c];
                float2 bb = *(const float2*)&sm[S_EB1 + c];
                float v0 = acc[nn][0] + p1.x + q1.x + bb.x;
                float v1 = acc[nn][1] + p1.y + q1.y + bb.y;
                float v2 = acc[nn][2] + p2.x + q2.x + bb.x;
                float v3 = acc[nn][3] + p2.y + q2.y + bb.y;
                acc[nn][0] = __uint_as_float(f32_to_tf32(fmaxf(v0, 0.f)));
                acc[nn][1] = __uint_as_float(f32_to_tf32(fmaxf(v1, 0.f)));
                acc[nn][2] = __uint_as_float(f32_to_tf32(fmaxf(v2, 0.f)));
                acc[nn][3] = __uint_as_float(f32_to_tf32(fmaxf(v3, 0.f)));
            }
        }

        // ---- quad-shuffle: accum layout (cols 2ct,2ct+1) -> A-frag (ct,ct+4) ----
        #pragma unroll
        for (int kk = 0; kk < 16; kk++) {
            float t0 = __shfl_sync(0xffffffffu, acc[kk][0], s0, 4);
            float t1 = __shfl_sync(0xffffffffu, acc[kk][1], s0, 4);
            float t2 = __shfl_sync(0xffffffffu, acc[kk][2], s0, 4);
            float t3 = __shfl_sync(0xffffffffu, acc[kk][3], s0, 4);
            float u0 = __shfl_sync(0xffffffffu, acc[kk][0], s1, 4);
            float u1 = __shfl_sync(0xffffffffu, acc[kk][1], s1, 4);
            float u2 = __shfl_sync(0xffffffffu, acc[kk][2], s1, 4);
            float u3 = __shfl_sync(0xffffffffu, acc[kk][3], s1, 4);
            acc[kk][0] = sel ? t1 : t0;   // (row gr,   col ct)
            acc[kk][1] = sel ? t3 : t2;   // (row gr+8, col ct)
            acc[kk][2] = sel ? u1 : u0;   // (row gr,   col ct+4)
            acc[kk][3] = sel ? u3 : u2;   // (row gr+8, col ct+4)
        }

        // ---- layer-2 mma: C2[16,64] per warp (A = H in registers) ----
        float acc2[8][4];
        #pragma unroll
        for (int nn = 0; nn < 8; nn++) {
            acc2[nn][0] = acc2[nn][1] = acc2[nn][2] = acc2[nn][3] = 0.f;
        }
        #pragma unroll
        for (int kk = 0; kk < 16; kk++) {
            uint32_t a[4];
            a[0] = __float_as_uint(acc[kk][0]);
            a[1] = __float_as_uint(acc[kk][1]);
            a[2] = __float_as_uint(acc[kk][2]);
            a[3] = __float_as_uint(acc[kk][3]);
            #pragma unroll
            for (int nn = 0; nn < 8; nn++) {
                uint32_t b[2];
                const uint2 bv = *(const uint2*)&smu[S_B2 + (kk * 8 + nn) * 66 + lane * 2];
                b[0] = bv.x; b[1] = bv.y;
                mma_tf32(acc2[nn], a, b);
            }
        }

        // ---- output: out_edge stores + red.v2 scatter (fragment layout) ----
        {
            float* op1 = out_edge + (size_t)(e0 + r1) * 64;
            float* op2 = out_edge + (size_t)(e0 + r2) * 64;
            float* mp1 = g_msg + (size_t)ce1 * 64;
            float* mp2 = g_msg + (size_t)ce2 * 64;
            #pragma unroll
            for (int nn = 0; nn < 8; nn++) {
                int c = nn * 8 + 2 * ct;
                float2 bb = *(const float2*)&sm[S_EB2 + c];
                float2 o1 = make_float2(acc2[nn][0] + bb.x, acc2[nn][1] + bb.y);
                float2 o2 = make_float2(acc2[nn][2] + bb.x, acc2[nn][3] + bb.y);
                *(float2*)(op1 + c) = o1;
                *(float2*)(op2 + c) = o2;
                asm volatile("red.global.add.v2.f32 [%0], {%1,%2};"
                             :: "l"(mp1 + c), "f"(o1.x), "f"(o1.y) : "memory");
                asm volatile("red.global.add.v2.f32 [%0], {%1,%2};"
                             :: "l"(mp2 + c), "f"(o2.x), "f"(o2.y) : "memory");
            }
        }

        CP_WAIT0();
        __syncthreads();
    }
}

// ---------------------------------------------------------------------------
// Node kernel (fp32): x_new = relu([x|msg]@nW1 + nb1) @ nW2 + nb2
// ---------------------------------------------------------------------------
__global__ void __launch_bounds__(256, 2) node_kernel(
    const float* __restrict__ x,
    const float* __restrict__ nW1, const float* __restrict__ nb1,
    const float* __restrict__ nW2, const float* __restrict__ nb2,
    float* __restrict__ out_node)
{
    extern __shared__ float sm[];
    float* buf = sm;                      // [64][132]
    float* W1s = buf + 64 * 132;          // [64][128]
    float* W2s = W1s + 64 * 128;          // [128][64]

    const int n0  = blockIdx.x * 64;
    const int tid = threadIdx.x;

    for (int idx = tid; idx < 64 * 128; idx += 256) {
        int r = idx >> 7, c = idx & 127;
        int n = n0 + r;
        float v = 0.f;
        if (n < NN) v = (c < 64) ? x[n * 64 + c] : g_msg[n * 64 + (c - 64)];
        buf[r * 132 + c] = v;
    }
    for (int idx = tid; idx < 128 * 64; idx += 256) W2s[idx] = nW2[idx];

    const int tx = tid & 15;
    const int ty = tid >> 4;

    float acc[4][8];
    #pragma unroll
    for (int i = 0; i < 4; i++)
        #pragma unroll
        for (int j = 0; j < 8; j++) acc[i][j] = 0.f;

    #pragma unroll
    for (int half = 0; half < 2; half++) {
        for (int idx = tid; idx < 64 * 128; idx += 256)
            W1s[idx] = nW1[half * 64 * 128 + idx];
        __syncthreads();

        #pragma unroll 4
        for (int k = 0; k < 64; k++) {
            float a[4];
            #pragma unroll
            for (int i = 0; i < 4; i++)
                a[i] = buf[(ty * 4 + i) * 132 + half * 64 + k];
            const float4 b0 = *(const float4*)&W1s[k * 128 + tx * 8 + 0];
            const float4 b1 = *(const float4*)&W1s[k * 128 + tx * 8 + 4];
            float b[8] = {b0.x, b0.y, b0.z, b0.w, b1.x, b1.y, b1.z, b1.w};
            #pragma unroll
            for (int i = 0; i < 4; i++)
                #pragma unroll
                for (int j = 0; j < 8; j++)
                    acc[i][j] = fmaf(a[i], b[j], acc[i][j]);
        }
        __syncthreads();
    }

    const float4 n1a = *(const float4*)&nb1[tx * 8 + 0];
    const float4 n1b = *(const float4*)&nb1[tx * 8 + 4];
    float bias1[8] = {n1a.x, n1a.y, n1a.z, n1a.w, n1b.x, n1b.y, n1b.z, n1b.w};
    #pragma unroll
    for (int i = 0; i < 4; i++) {
        float h[8];
        #pragma unroll
        for (int j = 0; j < 8; j++) {
            float v = acc[i][j] + bias1[j];
            h[j] = v > 0.f ? v : 0.f;
        }
        float* hp = &buf[(ty * 4 + i) * 132 + tx * 8];
        *(float4*)(hp + 0) = make_float4(h[0], h[1], h[2], h[3]);
        *(float4*)(hp + 4) = make_float4(h[4], h[5], h[6], h[7]);
    }
    __syncthreads();

    float acc2[4][4];
    #pragma unroll
    for (int i = 0; i < 4; i++)
        #pragma unroll
        for (int j = 0; j < 4; j++) acc2[i][j] = 0.f;

    #pragma unroll 4
    for (int k = 0; k < 128; k++) {
        float a[4];
        #pragma unroll
        for (int i = 0; i < 4; i++) a[i] = buf[(ty * 4 + i) * 132 + k];
        const float4 b = *(const float4*)&W2s[k * 64 + tx * 4];
        #pragma unroll
        for (int i = 0; i < 4; i++) {
            acc2[i][0] = fmaf(a[i], b.x, acc2[i][0]);
            acc2[i][1] = fmaf(a[i], b.y, acc2[i][1]);
            acc2[i][2] = fmaf(a[i], b.z, acc2[i][2]);
            acc2[i][3] = fmaf(a[i], b.w, acc2[i][3]);
        }
    }

    const float4 b2 = *(const float4*)&nb2[tx * 4];
    #pragma unroll
    for (int i = 0; i < 4; i++) {
        int n = n0 + ty * 4 + i;
        if (n >= NN) continue;
        float4 o = make_float4(acc2[i][0] + b2.x, acc2[i][1] + b2.y,
                               acc2[i][2] + b2.z, acc2[i][3] + b2.w);
        *(float4*)&out_node[n * 64 + tx * 4] = o;
    }
}

// ---------------------------------------------------------------------------
extern "C" void kernel_launch(void* const* d_in, const int* in_sizes, int n_in,
                              void* d_out, int out_size)
{
    const float* x    = (const float*)d_in[0];
    const int*   ei   = (const int*)  d_in[1];
    const float* ea   = (const float*)d_in[2];
    const float* eW1  = (const float*)d_in[3];
    const float* eb1  = (const float*)d_in[4];
    const float* eW2  = (const float*)d_in[5];
    const float* eb2  = (const float*)d_in[6];
    const float* nW1  = (const float*)d_in[7];
    const float* nb1  = (const float*)d_in[8];
    const float* nW2  = (const float*)d_in[9];
    const float* nb2  = (const float*)d_in[10];

    float* out_node = (float*)d_out;             // [NN, 64]
    float* out_edge = (float*)d_out + NN * ND;   // [NE, 64]

    const int smem_pre  = (64 * 68 + 64 * 256) * 4;             // 82944
    const int smem_node = (64 * 132 + 64 * 128 + 128 * 64) * 4; // 99328

    cudaFuncSetAttribute(precompute_kernel,
        cudaFuncAttributeMaxDynamicSharedMemorySize, smem_pre);
    cudaFuncSetAttribute(edge_kernel,
        cudaFuncAttributeMaxDynamicSharedMemorySize, EDGE_SMEM_BYTES);
    cudaFuncSetAttribute(node_kernel,
        cudaFuncAttributeMaxDynamicSharedMemorySize, smem_node);

    zero_msg_kernel<<<(NN * ED / 4) / 256, 256>>>();
    precompute_kernel<<<(NN + 63) / 64, 256, smem_pre>>>(x, eW1);
    edge_kernel<<<EDGE_GRID, 256, EDGE_SMEM_BYTES>>>(ea, ei, eW1, eb1, eW2, eb2, out_edge);
    node_kernel<<<(NN + 63) / 64, 256, smem_node>>>(x, nW1, nb1, nW2, nb2, out_node);
}

// round 9
// speedup vs baseline: 3.6268x; 1.0664x over previous
#include <cuda_runtime.h>
#include <cstdint>

// Problem constants
constexpr int NN  = 50000;   // nodes
constexpr int NE  = 800000;  // edges
constexpr int ND  = 64;      // node dim
constexpr int ED  = 64;      // edge dim
constexpr int HID = 128;     // hidden

constexpr int NTILES = NE / 128;            // 6250 edge tiles
constexpr int NTILN  = (NN + 127) / 128;    // 391 node tiles
constexpr int PGRID  = 296;                 // 2 CTAs x 148 SMs, persistent

// Scratch (device globals: allocation-free)
__device__ float g_PR[NN * HID];   // x @ eW1[64:128]   (fp32 exact)
__device__ float g_PC[NN * HID];   // x @ eW1[128:192]  (fp32 exact)
__device__ float g_PX[NN * HID];   // x @ nW1[0:64]     (fp32 exact)
__device__ float g_msg[NN * ED];   // scatter-add accumulator

// ---------------------------------------------------------------------------
// helpers
// ---------------------------------------------------------------------------
__device__ __forceinline__ uint32_t f32_to_tf32(float f) {
    uint32_t u;
    asm("cvt.rna.tf32.f32 %0, %1;" : "=r"(u) : "f"(f));
    return u;
}

__device__ __forceinline__ void mma_tf32(float d[4], const uint32_t a[4],
                                         const uint32_t b[2]) {
    asm volatile(
        "mma.sync.aligned.m16n8k8.row.col.f32.tf32.tf32.f32 "
        "{%0,%1,%2,%3}, {%4,%5,%6,%7}, {%8,%9}, {%0,%1,%2,%3};"
        : "+f"(d[0]), "+f"(d[1]), "+f"(d[2]), "+f"(d[3])
        : "r"(a[0]), "r"(a[1]), "r"(a[2]), "r"(a[3]), "r"(b[0]), "r"(b[1]));
}

__device__ __forceinline__ uint32_t smem_u32(const void* p) {
    uint32_t a;
    asm("{ .reg .u64 t; cvta.to.shared.u64 t, %1; cvt.u32.u64 %0, t; }"
        : "=r"(a) : "l"(p));
    return a;
}

#define CP_ASYNC16(dst_u32, src_ptr) \
    asm volatile("cp.async.cg.shared.global [%0], [%1], 16;" \
                 :: "r"(dst_u32), "l"(src_ptr))
#define CP_ASYNC16_Z(dst_u32, src_ptr, src_bytes) \
    asm volatile("cp.async.cg.shared.global [%0], [%1], 16, %2;" \
                 :: "r"(dst_u32), "l"(src_ptr), "r"(src_bytes))
#define CP_COMMIT()  asm volatile("cp.async.commit_group;")
#define CP_WAIT0()   asm volatile("cp.async.wait_group 0;" ::: "memory")

// ---------------------------------------------------------------------------
__global__ void zero_msg_kernel() {
    int i = blockIdx.x * blockDim.x + threadIdx.x;
    reinterpret_cast<float4*>(g_msg)[i] = make_float4(0.f, 0.f, 0.f, 0.f);
}

// ---------------------------------------------------------------------------
// Precompute PR/PC (fp32 exact): GEMM [NN,64] @ [64,256]
// ---------------------------------------------------------------------------
__global__ void __launch_bounds__(256, 2) precompute_kernel(
    const float* __restrict__ x, const float* __restrict__ eW1)
{
    extern __shared__ float sm[];
    float* Xs = sm;               // [64][68]
    float* Ws = sm + 64 * 68;     // [64][256]

    const int n0 = blockIdx.x * 64;
    const int tid = threadIdx.x;

    for (int idx = tid; idx < 64 * 64; idx += 256) {
        int r = idx >> 6, c = idx & 63;
        int n = n0 + r;
        Xs[r * 68 + c] = (n < NN) ? x[n * 64 + c] : 0.f;
    }
    for (int idx = tid; idx < 64 * 256; idx += 256) {
        int k = idx >> 8, j = idx & 255;
        float v = (j < 128) ? eW1[(64 + k) * 128 + j]
                            : eW1[(128 + k) * 128 + (j - 128)];
        Ws[k * 256 + j] = v;
    }
    __syncthreads();

    const int tx = tid & 15;
    const int ty = tid >> 4;

    float acc[4][16];
    #pragma unroll
    for (int i = 0; i < 4; i++)
        #pragma unroll
        for (int j = 0; j < 16; j++) acc[i][j] = 0.f;

    #pragma unroll 4
    for (int k = 0; k < 64; k++) {
        float a[4];
        #pragma unroll
        for (int i = 0; i < 4; i++) a[i] = Xs[(ty * 4 + i) * 68 + k];
        const float4 b0 = *(const float4*)&Ws[k * 256 + tx * 16 + 0];
        const float4 b1 = *(const float4*)&Ws[k * 256 + tx * 16 + 4];
        const float4 b2 = *(const float4*)&Ws[k * 256 + tx * 16 + 8];
        const float4 b3 = *(const float4*)&Ws[k * 256 + tx * 16 + 12];
        float b[16] = {b0.x, b0.y, b0.z, b0.w, b1.x, b1.y, b1.z, b1.w,
                       b2.x, b2.y, b2.z, b2.w, b3.x, b3.y, b3.z, b3.w};
        #pragma unroll
        for (int i = 0; i < 4; i++)
            #pragma unroll
            for (int j = 0; j < 16; j++)
                acc[i][j] = fmaf(a[i], b[j], acc[i][j]);
    }

    float* dst = (tx < 8) ? g_PR : g_PC;
    int    cb  = (tx < 8) ? tx * 16 : (tx - 8) * 16;
    #pragma unroll
    for (int i = 0; i < 4; i++) {
        int n = n0 + ty * 4 + i;
        if (n >= NN) continue;
        #pragma unroll
        for (int j = 0; j < 16; j += 4) {
            float4 o = make_float4(acc[i][j], acc[i][j + 1],
                                   acc[i][j + 2], acc[i][j + 3]);
            *(float4*)&dst[n * 128 + cb + j] = o;
        }
    }
}

// ---------------------------------------------------------------------------
// Precompute PX (fp32 exact): PX = x @ nW1[0:64]   [NN,128]
// ---------------------------------------------------------------------------
__global__ void __launch_bounds__(256, 2) precompute_px_kernel(
    const float* __restrict__ x, const float* __restrict__ nW1)
{
    extern __shared__ float sm[];
    float* Xs = sm;               // [64][68]
    float* Ws = sm + 64 * 68;     // [64][128]

    const int n0 = blockIdx.x * 64;
    const int tid = threadIdx.x;

    for (int idx = tid; idx < 64 * 64; idx += 256) {
        int r = idx >> 6, c = idx & 63;
        int n = n0 + r;
        Xs[r * 68 + c] = (n < NN) ? x[n * 64 + c] : 0.f;
    }
    for (int idx = tid; idx < 64 * 128; idx += 256)
        Ws[idx] = nW1[idx];       // rows 0..63 of nW1
    __syncthreads();

    const int tx = tid & 15;
    const int ty = tid >> 4;

    float acc[4][8];
    #pragma unroll
    for (int i = 0; i < 4; i++)
        #pragma unroll
        for (int j = 0; j < 8; j++) acc[i][j] = 0.f;

    #pragma unroll 4
    for (int k = 0; k < 64; k++) {
        float a[4];
        #pragma unroll
        for (int i = 0; i < 4; i++) a[i] = Xs[(ty * 4 + i) * 68 + k];
        const float4 b0 = *(const float4*)&Ws[k * 128 + tx * 8 + 0];
        const float4 b1 = *(const float4*)&Ws[k * 128 + tx * 8 + 4];
        float b[8] = {b0.x, b0.y, b0.z, b0.w, b1.x, b1.y, b1.z, b1.w};
        #pragma unroll
        for (int i = 0; i < 4; i++)
            #pragma unroll
            for (int j = 0; j < 8; j++)
                acc[i][j] = fmaf(a[i], b[j], acc[i][j]);
    }

    #pragma unroll
    for (int i = 0; i < 4; i++) {
        int n = n0 + ty * 4 + i;
        if (n >= NN) continue;
        *(float4*)&g_PX[n * 128 + tx * 8 + 0] =
            make_float4(acc[i][0], acc[i][1], acc[i][2], acc[i][3]);
        *(float4*)&g_PX[n * 128 + tx * 8 + 4] =
            make_float4(acc[i][4], acc[i][5], acc[i][6], acc[i][7]);
    }
}

// ---------------------------------------------------------------------------
// Shared smem layout for the two persistent mma kernels (103168 B, 2 CTAs/SM)
// ---------------------------------------------------------------------------
constexpr int S_A   = 0;          // A [128][68] row-major (raw fp32)
constexpr int S_B1  = 8704;       // B1frag [pane=kk*16+nn][66]
constexpr int S_B2  = 17152;      // B2frag [pane=kk*8+nn][66]
constexpr int S_EB1 = 25600;      // bias1 [128]
constexpr int S_EB2 = 25728;      // bias2 [64]
constexpr int MMA_SMEM_BYTES = 25792 * 4;

// ---------------------------------------------------------------------------
// Edge kernel — persistent, tf32 mma.sync, cp.async prefetch, register-H.
// ---------------------------------------------------------------------------
__global__ void __launch_bounds__(256, 2) edge_kernel(
    const float* __restrict__ edge_attr,
    const int*   __restrict__ edge_index,   // [2][NE]
    const float* __restrict__ eW1,
    const float* __restrict__ eb1,
    const float* __restrict__ eW2,
    const float* __restrict__ eb2,
    float* __restrict__ out_edge)
{
    extern __shared__ float sm[];
    uint32_t* smu = reinterpret_cast<uint32_t*>(sm);
    const uint32_t sbase = smem_u32(sm);

    const int tid  = threadIdx.x;
    const int lane = tid & 31;
    const int w    = tid >> 5;
    const int gr   = lane >> 2;
    const int ct   = lane & 3;
    const int s0   = ct >> 1;
    const int s1   = 2 + (ct >> 1);
    const int sel  = ct & 1;
    const int even = (ct & 1) == 0;
    const int qb   = 4 * (ct >> 1);       // quad col base within octet
    const int r1   = 16 * w + gr;
    const int r2   = r1 + 8;

    int tile = blockIdx.x;

    // ---- prologue ----
    {
        int e0 = tile * 128;
        for (int t = tid; t < 2048; t += 256) {
            int row = t >> 4, c4 = (t & 15) << 2;
            CP_ASYNC16(sbase + (S_A + row * 68 + c4) * 4,
                       edge_attr + (size_t)(e0 + row) * 64 + c4);
        }
    }
    CP_COMMIT();

    for (int t = tid; t < 2048; t += 256) {
        int k = t >> 5, n4 = (t & 31) << 2;
        float4 v = *(const float4*)&eW1[k * 128 + n4];
        int pane = (k >> 3) * 16 + (n4 >> 3);
        int j    = (k >> 2) & 1;
        int ln0  = ((n4 & 7) << 2) | (k & 3);
        uint32_t* p = &smu[S_B1 + pane * 66 + j];
        p[(ln0 + 0)  * 2] = f32_to_tf32(v.x);
        p[(ln0 + 4)  * 2] = f32_to_tf32(v.y);
        p[(ln0 + 8)  * 2] = f32_to_tf32(v.z);
        p[(ln0 + 12) * 2] = f32_to_tf32(v.w);
    }
    for (int t = tid; t < 2048; t += 256) {
        int k = t >> 4, n4 = (t & 15) << 2;
        float4 v = *(const float4*)&eW2[k * 64 + n4];
        int pane = (k >> 3) * 8 + (n4 >> 3);
        int j    = (k >> 2) & 1;
        int ln0  = ((n4 & 7) << 2) | (k & 3);
        uint32_t* p = &smu[S_B2 + pane * 66 + j];
        p[(ln0 + 0)  * 2] = f32_to_tf32(v.x);
        p[(ln0 + 4)  * 2] = f32_to_tf32(v.y);
        p[(ln0 + 8)  * 2] = f32_to_tf32(v.z);
        p[(ln0 + 12) * 2] = f32_to_tf32(v.w);
    }
    if (tid < 128) sm[S_EB1 + tid] = eb1[tid];
    if (tid < 64)  sm[S_EB2 + tid] = eb2[tid];

    CP_WAIT0();
    __syncthreads();

    // ---- persistent tile loop ----
    for (; tile < NTILES; tile += PGRID) {
        const int e0 = tile * 128;

        const int re1 = edge_index[e0 + r1];
        const int re2 = edge_index[e0 + r2];
        const int ce1 = edge_index[NE + e0 + r1];
        const int ce2 = edge_index[NE + e0 + r2];

        // layer-1 mma
        float acc[16][4];
        #pragma unroll
        for (int nn = 0; nn < 16; nn++) {
            acc[nn][0] = acc[nn][1] = acc[nn][2] = acc[nn][3] = 0.f;
        }
        #pragma unroll
        for (int kk = 0; kk < 8; kk++) {
            uint32_t a[4];
            a[0] = smu[S_A + r1 * 68 + kk * 8 + ct];
            a[1] = smu[S_A + r2 * 68 + kk * 8 + ct];
            a[2] = smu[S_A + r1 * 68 + kk * 8 + ct + 4];
            a[3] = smu[S_A + r2 * 68 + kk * 8 + ct + 4];
            #pragma unroll
            for (int nn = 0; nn < 16; nn++) {
                uint32_t b[2];
                const uint2 bv = *(const uint2*)&smu[S_B1 + (kk * 16 + nn) * 66 + lane * 2];
                b[0] = bv.x; b[1] = bv.y;
                mma_tf32(acc[nn], a, b);
            }
        }
        __syncthreads();

        // prefetch next A
        {
            int ntile = tile + PGRID;
            if (ntile < NTILES) {
                int ne0 = ntile * 128;
                for (int t = tid; t < 2048; t += 256) {
                    int row = t >> 4, c4 = (t & 15) << 2;
                    CP_ASYNC16(sbase + (S_A + row * 68 + c4) * 4,
                               edge_attr + (size_t)(ne0 + row) * 64 + c4);
                }
            }
            CP_COMMIT();
        }

        // epilogue: H = rna(relu(C1 + PR + PC + eb1))
        {
            const float* PR1 = g_PR + (size_t)re1 * 128;
            const float* PR2 = g_PR + (size_t)re2 * 128;
            const float* PC1 = g_PC + (size_t)ce1 * 128;
            const float* PC2 = g_PC + (size_t)ce2 * 128;
            #pragma unroll
            for (int nn = 0; nn < 16; nn++) {
                int c = nn * 8 + 2 * ct;
                float2 p1 = *(const float2*)&PR1[c];
                float2 q1 = *(const float2*)&PC1[c];
                float2 p2 = *(const float2*)&PR2[c];
                float2 q2 = *(const float2*)&PC2[c];
                float2 bb = *(const float2*)&sm[S_EB1 + c];
                float v0 = acc[nn][0] + p1.x + q1.x + bb.x;
                float v1 = acc[nn][1] + p1.y + q1.y + bb.y;
                float v2 = acc[nn][2] + p2.x + q2.x + bb.x;
                float v3 = acc[nn][3] + p2.y + q2.y + bb.y;
                acc[nn][0] = __uint_as_float(f32_to_tf32(fmaxf(v0, 0.f)));
                acc[nn][1] = __uint_as_float(f32_to_tf32(fmaxf(v1, 0.f)));
                acc[nn][2] = __uint_as_float(f32_to_tf32(fmaxf(v2, 0.f)));
                acc[nn][3] = __uint_as_float(f32_to_tf32(fmaxf(v3, 0.f)));
            }
        }

        // quad-shuffle transpose -> layer-2 A fragments
        #pragma unroll
        for (int kk = 0; kk < 16; kk++) {
            float t0 = __shfl_sync(0xffffffffu, acc[kk][0], s0, 4);
            float t1 = __shfl_sync(0xffffffffu, acc[kk][1], s0, 4);
            float t2 = __shfl_sync(0xffffffffu, acc[kk][2], s0, 4);
            float t3 = __shfl_sync(0xffffffffu, acc[kk][3], s0, 4);
            float u0 = __shfl_sync(0xffffffffu, acc[kk][0], s1, 4);
            float u1 = __shfl_sync(0xffffffffu, acc[kk][1], s1, 4);
            float u2 = __shfl_sync(0xffffffffu, acc[kk][2], s1, 4);
            float u3 = __shfl_sync(0xffffffffu, acc[kk][3], s1, 4);
            acc[kk][0] = sel ? t1 : t0;
            acc[kk][1] = sel ? t3 : t2;
            acc[kk][2] = sel ? u1 : u0;
            acc[kk][3] = sel ? u3 : u2;
        }

        // layer-2 mma
        float acc2[8][4];
        #pragma unroll
        for (int nn = 0; nn < 8; nn++) {
            acc2[nn][0] = acc2[nn][1] = acc2[nn][2] = acc2[nn][3] = 0.f;
        }
        #pragma unroll
        for (int kk = 0; kk < 16; kk++) {
            uint32_t a[4];
            a[0] = __float_as_uint(acc[kk][0]);
            a[1] = __float_as_uint(acc[kk][1]);
            a[2] = __float_as_uint(acc[kk][2]);
            a[3] = __float_as_uint(acc[kk][3]);
            #pragma unroll
            for (int nn = 0; nn < 8; nn++) {
                uint32_t b[2];
                const uint2 bv = *(const uint2*)&smu[S_B2 + (kk * 8 + nn) * 66 + lane * 2];
                b[0] = bv.x; b[1] = bv.y;
                mma_tf32(acc2[nn], a, b);
            }
        }

        // output: lane-pair exchange -> one float4 quad per thread per octet
        {
            const int row  = even ? r1 : r2;
            const int cerow = even ? ce1 : ce2;
            float* op = out_edge + (size_t)(e0 + row) * 64;
            float* mp = g_msg + (size_t)cerow * 64;
            #pragma unroll
            for (int nn = 0; nn < 8; nn++) {
                float sa = __shfl_xor_sync(0xffffffffu, acc2[nn][0], 1);
                float sb = __shfl_xor_sync(0xffffffffu, acc2[nn][1], 1);
                float sc = __shfl_xor_sync(0xffffffffu, acc2[nn][2], 1);
                float sd = __shfl_xor_sync(0xffffffffu, acc2[nn][3], 1);
                int base = nn * 8 + qb;
                float4 bb = *(const float4*)&sm[S_EB2 + base];
                float4 o;
                if (even) {
                    o = make_float4(acc2[nn][0] + bb.x, acc2[nn][1] + bb.y,
                                    sa + bb.z, sb + bb.w);
                } else {
                    o = make_float4(sc + bb.x, sd + bb.y,
                                    acc2[nn][2] + bb.z, acc2[nn][3] + bb.w);
                }
                *(float4*)(op + base) = o;
                asm volatile("red.global.add.v4.f32 [%0], {%1,%2,%3,%4};"
                             :: "l"(mp + base), "f"(o.x), "f"(o.y), "f"(o.z), "f"(o.w)
                             : "memory");
            }
        }

        CP_WAIT0();
        __syncthreads();
    }
}

// ---------------------------------------------------------------------------
// Node kernel — persistent tf32 mma, same skeleton, no gathers/atomics.
//   L1: C1[128,128] = msg[128,64] @ nW1b^T  (nW1 rows 64..127)
//   epi: H = rna(relu(C1 + PX[row] + nb1))
//   L2: out = H @ nW2 + nb2
// ---------------------------------------------------------------------------
__global__ void __launch_bounds__(256, 2) node_kernel(
    const float* __restrict__ nW1, const float* __restrict__ nb1,
    const float* __restrict__ nW2, const float* __restrict__ nb2,
    float* __restrict__ out_node)
{
    extern __shared__ float sm[];
    uint32_t* smu = reinterpret_cast<uint32_t*>(sm);
    const uint32_t sbase = smem_u32(sm);

    const int tid  = threadIdx.x;
    const int lane = tid & 31;
    const int w    = tid >> 5;
    const int gr   = lane >> 2;
    const int ct   = lane & 3;
    const int s0   = ct >> 1;
    const int s1   = 2 + (ct >> 1);
    const int sel  = ct & 1;
    const int even = (ct & 1) == 0;
    const int qb   = 4 * (ct >> 1);
    const int r1   = 16 * w + gr;
    const int r2   = r1 + 8;

    int tile = blockIdx.x;

    // prologue: A(tile0) from g_msg with zero-fill OOB rows
    {
        int n0 = tile * 128;
        for (int t = tid; t < 2048; t += 256) {
            int row = t >> 4, c4 = (t & 15) << 2;
            uint32_t nbytes = (n0 + row < NN) ? 16u : 0u;
            const float* src = g_msg + (size_t)min(n0 + row, NN - 1) * 64 + c4;
            CP_ASYNC16_Z(sbase + (S_A + row * 68 + c4) * 4, src, nbytes);
        }
    }
    CP_COMMIT();

    // B1 = nW1[64:128]^T fragments (K=64)
    for (int t = tid; t < 2048; t += 256) {
        int k = t >> 5, n4 = (t & 31) << 2;
        float4 v = *(const float4*)&nW1[(64 + k) * 128 + n4];
        int pane = (k >> 3) * 16 + (n4 >> 3);
        int j    = (k >> 2) & 1;
        int ln0  = ((n4 & 7) << 2) | (k & 3);
        uint32_t* p = &smu[S_B1 + pane * 66 + j];
        p[(ln0 + 0)  * 2] = f32_to_tf32(v.x);
        p[(ln0 + 4)  * 2] = f32_to_tf32(v.y);
        p[(ln0 + 8)  * 2] = f32_to_tf32(v.z);
        p[(ln0 + 12) * 2] = f32_to_tf32(v.w);
    }
    // B2 = nW2^T fragments (K=128)
    for (int t = tid; t < 2048; t += 256) {
        int k = t >> 4, n4 = (t & 15) << 2;
        float4 v = *(const float4*)&nW2[k * 64 + n4];
        int pane = (k >> 3) * 8 + (n4 >> 3);
        int j    = (k >> 2) & 1;
        int ln0  = ((n4 & 7) << 2) | (k & 3);
        uint32_t* p = &smu[S_B2 + pane * 66 + j];
        p[(ln0 + 0)  * 2] = f32_to_tf32(v.x);
        p[(ln0 + 4)  * 2] = f32_to_tf32(v.y);
        p[(ln0 + 8)  * 2] = f32_to_tf32(v.z);
        p[(ln0 + 12) * 2] = f32_to_tf32(v.w);
    }
    if (tid < 128) sm[S_EB1 + tid] = nb1[tid];
    if (tid < 64)  sm[S_EB2 + tid] = nb2[tid];

    CP_WAIT0();
    __syncthreads();

    for (; tile < NTILN; tile += PGRID) {
        const int n0 = tile * 128;

        // layer-1 mma (K=64)
        float acc[16][4];
        #pragma unroll
        for (int nn = 0; nn < 16; nn++) {
            acc[nn][0] = acc[nn][1] = acc[nn][2] = acc[nn][3] = 0.f;
        }
        #pragma unroll
        for (int kk = 0; kk < 8; kk++) {
            uint32_t a[4];
            a[0] = smu[S_A + r1 * 68 + kk * 8 + ct];
            a[1] = smu[S_A + r2 * 68 + kk * 8 + ct];
            a[2] = smu[S_A + r1 * 68 + kk * 8 + ct + 4];
            a[3] = smu[S_A + r2 * 68 + kk * 8 + ct + 4];
            #pragma unroll
            for (int nn = 0; nn < 16; nn++) {
                uint32_t b[2];
                const uint2 bv = *(const uint2*)&smu[S_B1 + (kk * 16 + nn) * 66 + lane * 2];
                b[0] = bv.x; b[1] = bv.y;
                mma_tf32(acc[nn], a, b);
            }
        }
        __syncthreads();

        // prefetch next tile
        {
            int ntile = tile + PGRID;
            if (ntile < NTILN) {
                int nn0 = ntile * 128;
                for (int t = tid; t < 2048; t += 256) {
                    int row = t >> 4, c4 = (t & 15) << 2;
                    uint32_t nbytes = (nn0 + row < NN) ? 16u : 0u;
                    const float* src = g_msg + (size_t)min(nn0 + row, NN - 1) * 64 + c4;
                    CP_ASYNC16_Z(sbase + (S_A + row * 68 + c4) * 4, src, nbytes);
                }
            }
            CP_COMMIT();
        }

        // epilogue: H = rna(relu(C1 + PX + nb1)); rows clamp (masked at store)
        {
            const float* PX1 = g_PX + (size_t)min(n0 + r1, NN - 1) * 128;
            const float* PX2 = g_PX + (size_t)min(n0 + r2, NN - 1) * 128;
            #pragma unroll
            for (int nn = 0; nn < 16; nn++) {
                int c = nn * 8 + 2 * ct;
                float2 p1 = *(const float2*)&PX1[c];
                float2 p2 = *(const float2*)&PX2[c];
                float2 bb = *(const float2*)&sm[S_EB1 + c];
                float v0 = acc[nn][0] + p1.x + bb.x;
                float v1 = acc[nn][1] + p1.y + bb.y;
                float v2 = acc[nn][2] + p2.x + bb.x;
                float v3 = acc[nn][3] + p2.y + bb.y;
                acc[nn][0] = __uint_as_float(f32_to_tf32(fmaxf(v0, 0.f)));
                acc[nn][1] = __uint_as_float(f32_to_tf32(fmaxf(v1, 0.f)));
                acc[nn][2] = __uint_as_float(f32_to_tf32(fmaxf(v2, 0.f)));
                acc[nn][3] = __uint_as_float(f32_to_tf32(fmaxf(v3, 0.f)));
            }
        }

        // quad-shuffle transpose
        #pragma unroll
        for (int kk = 0; kk < 16; kk++) {
            float t0 = __shfl_sync(0xffffffffu, acc[kk][0], s0, 4);
            float t1 = __shfl_sync(0xffffffffu, acc[kk][1], s0, 4);
            float t2 = __shfl_sync(0xffffffffu, acc[kk][2], s0, 4);
            float t3 = __shfl_sync(0xffffffffu, acc[kk][3], s0, 4);
            float u0 = __shfl_sync(0xffffffffu, acc[kk][0], s1, 4);
            float u1 = __shfl_sync(0xffffffffu, acc[kk][1], s1, 4);
            float u2 = __shfl_sync(0xffffffffu, acc[kk][2], s1, 4);
            float u3 = __shfl_sync(0xffffffffu, acc[kk][3], s1, 4);
            acc[kk][0] = sel ? t1 : t0;
            acc[kk][1] = sel ? t3 : t2;
            acc[kk][2] = sel ? u1 : u0;
            acc[kk][3] = sel ? u3 : u2;
        }

        // layer-2 mma (K=128)
        float acc2[8][4];
        #pragma unroll
        for (int nn = 0; nn < 8; nn++) {
            acc2[nn][0] = acc2[nn][1] = acc2[nn][2] = acc2[nn][3] = 0.f;
        }
        #pragma unroll
        for (int kk = 0; kk < 16; kk++) {
            uint32_t a[4];
            a[0] = __float_as_uint(acc[kk][0]);
            a[1] = __float_as_uint(acc[kk][1]);
            a[2] = __float_as_uint(acc[kk][2]);
            a[3] = __float_as_uint(acc[kk][3]);
            #pragma unroll
            for (int nn = 0; nn < 8; nn++) {
                uint32_t b[2];
                const uint2 bv = *(const uint2*)&smu[S_B2 + (kk * 8 + nn) * 66 + lane * 2];
                b[0] = bv.x; b[1] = bv.y;
                mma_tf32(acc2[nn], a, b);
            }
        }

        // output: exchange -> float4 stores (guarded)
        {
            const int row = even ? r1 : r2;
            const int n   = n0 + row;
            float* op = out_node + (size_t)n * 64;
            #pragma unroll
            for (int nn = 0; nn < 8; nn++) {
                float sa = __shfl_xor_sync(0xffffffffu, acc2[nn][0], 1);
                float sb = __shfl_xor_sync(0xffffffffu, acc2[nn][1], 1);
                float sc = __shfl_xor_sync(0xffffffffu, acc2[nn][2], 1);
                float sd = __shfl_xor_sync(0xffffffffu, acc2[nn][3], 1);
                int base = nn * 8 + qb;
                float4 bb = *(const float4*)&sm[S_EB2 + base];
                float4 o;
                if (even) {
                    o = make_float4(acc2[nn][0] + bb.x, acc2[nn][1] + bb.y,
                                    sa + bb.z, sb + bb.w);
                } else {
                    o = make_float4(sc + bb.x, sd + bb.y,
                                    acc2[nn][2] + bb.z, acc2[nn][3] + bb.w);
                }
                if (n < NN) *(float4*)(op + base) = o;
            }
        }

        CP_WAIT0();
        __syncthreads();
    }
}

// ---------------------------------------------------------------------------
extern "C" void kernel_launch(void* const* d_in, const int* in_sizes, int n_in,
                              void* d_out, int out_size)
{
    const float* x    = (const float*)d_in[0];
    const int*   ei   = (const int*)  d_in[1];
    const float* ea   = (const float*)d_in[2];
    const float* eW1  = (const float*)d_in[3];
    const float* eb1  = (const float*)d_in[4];
    const float* eW2  = (const float*)d_in[5];
    const float* eb2  = (const float*)d_in[6];
    const float* nW1  = (const float*)d_in[7];
    const float* nb1  = (const float*)d_in[8];
    const float* nW2  = (const float*)d_in[9];
    const float* nb2  = (const float*)d_in[10];

    float* out_node = (float*)d_out;             // [NN, 64]
    float* out_edge = (float*)d_out + NN * ND;   // [NE, 64]

    const int smem_pre = (64 * 68 + 64 * 256) * 4;   // 82944
    const int smem_px  = (64 * 68 + 64 * 128) * 4;   // 50176

    cudaFuncSetAttribute(precompute_kernel,
        cudaFuncAttributeMaxDynamicSharedMemorySize, smem_pre);
    cudaFuncSetAttribute(precompute_px_kernel,
        cudaFuncAttributeMaxDynamicSharedMemorySize, smem_px);
    cudaFuncSetAttribute(edge_kernel,
        cudaFuncAttributeMaxDynamicSharedMemorySize, MMA_SMEM_BYTES);
    cudaFuncSetAttribute(node_kernel,
        cudaFuncAttributeMaxDynamicSharedMemorySize, MMA_SMEM_BYTES);

    zero_msg_kernel<<<(NN * ED / 4) / 256, 256>>>();
    precompute_kernel<<<(NN + 63) / 64, 256, smem_pre>>>(x, eW1);
    precompute_px_kernel<<<(NN + 63) / 64, 256, smem_px>>>(x, nW1);
    edge_kernel<<<PGRID, 256, MMA_SMEM_BYTES>>>(ea, ei, eW1, eb1, eW2, eb2, out_edge);
    node_kernel<<<PGRID, 256, MMA_SMEM_BYTES>>>(nW1, nb1, nW2, nb2, out_node);
}

// round 10
// speedup vs baseline: 3.6690x; 1.0116x over previous
#include <cuda_runtime.h>
#include <cstdint>

// Problem constants
constexpr int NN  = 50000;   // nodes
constexpr int NE  = 800000;  // edges
constexpr int ND  = 64;      // node dim
constexpr int ED  = 64;      // edge dim
constexpr int HID = 128;     // hidden

constexpr int NTILES = NE / 128;            // 6250 edge tiles
constexpr int NTILN  = (NN + 127) / 128;    // 391 node tiles
constexpr int PGRID  = 296;                 // persistent grid

// Scratch (device globals: allocation-free)
__device__ float g_PR[NN * HID];   // x @ eW1[64:128]   (fp32 exact)
__device__ float g_PC[NN * HID];   // x @ eW1[128:192]  (fp32 exact)
__device__ float g_PX[NN * HID];   // x @ nW1[0:64]     (fp32 exact)
__device__ float g_msg[NN * ED];   // scatter-add accumulator

// ---------------------------------------------------------------------------
// helpers
// ---------------------------------------------------------------------------
__device__ __forceinline__ uint32_t f32_to_tf32(float f) {
    uint32_t u;
    asm("cvt.rna.tf32.f32 %0, %1;" : "=r"(u) : "f"(f));
    return u;
}

__device__ __forceinline__ void mma_tf32(float d[4], const uint32_t a[4],
                                         const uint32_t b[2]) {
    asm volatile(
        "mma.sync.aligned.m16n8k8.row.col.f32.tf32.tf32.f32 "
        "{%0,%1,%2,%3}, {%4,%5,%6,%7}, {%8,%9}, {%0,%1,%2,%3};"
        : "+f"(d[0]), "+f"(d[1]), "+f"(d[2]), "+f"(d[3])
        : "r"(a[0]), "r"(a[1]), "r"(a[2]), "r"(a[3]), "r"(b[0]), "r"(b[1]));
}

__device__ __forceinline__ uint32_t smem_u32(const void* p) {
    uint32_t a;
    asm("{ .reg .u64 t; cvta.to.shared.u64 t, %1; cvt.u32.u64 %0, t; }"
        : "=r"(a) : "l"(p));
    return a;
}

#define CP_ASYNC16(dst_u32, src_ptr) \
    asm volatile("cp.async.cg.shared.global [%0], [%1], 16;" \
                 :: "r"(dst_u32), "l"(src_ptr))
#define CP_ASYNC16_Z(dst_u32, src_ptr, src_bytes) \
    asm volatile("cp.async.cg.shared.global [%0], [%1], 16, %2;" \
                 :: "r"(dst_u32), "l"(src_ptr), "r"(src_bytes))
#define CP_COMMIT()  asm volatile("cp.async.commit_group;")
#define CP_WAIT0()   asm volatile("cp.async.wait_group 0;" ::: "memory")

// ---------------------------------------------------------------------------
__global__ void zero_msg_kernel() {
    int i = blockIdx.x * blockDim.x + threadIdx.x;
    reinterpret_cast<float4*>(g_msg)[i] = make_float4(0.f, 0.f, 0.f, 0.f);
}

// ---------------------------------------------------------------------------
// Precompute PR/PC (fp32 exact): GEMM [NN,64] @ [64,256]
// ---------------------------------------------------------------------------
__global__ void __launch_bounds__(256, 2) precompute_kernel(
    const float* __restrict__ x, const float* __restrict__ eW1)
{
    extern __shared__ float sm[];
    float* Xs = sm;               // [64][68]
    float* Ws = sm + 64 * 68;     // [64][256]

    const int n0 = blockIdx.x * 64;
    const int tid = threadIdx.x;

    for (int idx = tid; idx < 64 * 64; idx += 256) {
        int r = idx >> 6, c = idx & 63;
        int n = n0 + r;
        Xs[r * 68 + c] = (n < NN) ? x[n * 64 + c] : 0.f;
    }
    for (int idx = tid; idx < 64 * 256; idx += 256) {
        int k = idx >> 8, j = idx & 255;
        float v = (j < 128) ? eW1[(64 + k) * 128 + j]
                            : eW1[(128 + k) * 128 + (j - 128)];
        Ws[k * 256 + j] = v;
    }
    __syncthreads();

    const int tx = tid & 15;
    const int ty = tid >> 4;

    float acc[4][16];
    #pragma unroll
    for (int i = 0; i < 4; i++)
        #pragma unroll
        for (int j = 0; j < 16; j++) acc[i][j] = 0.f;

    #pragma unroll 4
    for (int k = 0; k < 64; k++) {
        float a[4];
        #pragma unroll
        for (int i = 0; i < 4; i++) a[i] = Xs[(ty * 4 + i) * 68 + k];
        const float4 b0 = *(const float4*)&Ws[k * 256 + tx * 16 + 0];
        const float4 b1 = *(const float4*)&Ws[k * 256 + tx * 16 + 4];
        const float4 b2 = *(const float4*)&Ws[k * 256 + tx * 16 + 8];
        const float4 b3 = *(const float4*)&Ws[k * 256 + tx * 16 + 12];
        float b[16] = {b0.x, b0.y, b0.z, b0.w, b1.x, b1.y, b1.z, b1.w,
                       b2.x, b2.y, b2.z, b2.w, b3.x, b3.y, b3.z, b3.w};
        #pragma unroll
        for (int i = 0; i < 4; i++)
            #pragma unroll
            for (int j = 0; j < 16; j++)
                acc[i][j] = fmaf(a[i], b[j], acc[i][j]);
    }

    float* dst = (tx < 8) ? g_PR : g_PC;
    int    cb  = (tx < 8) ? tx * 16 : (tx - 8) * 16;
    #pragma unroll
    for (int i = 0; i < 4; i++) {
        int n = n0 + ty * 4 + i;
        if (n >= NN) continue;
        #pragma unroll
        for (int j = 0; j < 16; j += 4) {
            float4 o = make_float4(acc[i][j], acc[i][j + 1],
                                   acc[i][j + 2], acc[i][j + 3]);
            *(float4*)&dst[n * 128 + cb + j] = o;
        }
    }
}

// ---------------------------------------------------------------------------
// Precompute PX (fp32 exact): PX = x @ nW1[0:64]   [NN,128]
// ---------------------------------------------------------------------------
__global__ void __launch_bounds__(256, 2) precompute_px_kernel(
    const float* __restrict__ x, const float* __restrict__ nW1)
{
    extern __shared__ float sm[];
    float* Xs = sm;               // [64][68]
    float* Ws = sm + 64 * 68;     // [64][128]

    const int n0 = blockIdx.x * 64;
    const int tid = threadIdx.x;

    for (int idx = tid; idx < 64 * 64; idx += 256) {
        int r = idx >> 6, c = idx & 63;
        int n = n0 + r;
        Xs[r * 68 + c] = (n < NN) ? x[n * 64 + c] : 0.f;
    }
    for (int idx = tid; idx < 64 * 128; idx += 256)
        Ws[idx] = nW1[idx];
    __syncthreads();

    const int tx = tid & 15;
    const int ty = tid >> 4;

    float acc[4][8];
    #pragma unroll
    for (int i = 0; i < 4; i++)
        #pragma unroll
        for (int j = 0; j < 8; j++) acc[i][j] = 0.f;

    #pragma unroll 4
    for (int k = 0; k < 64; k++) {
        float a[4];
        #pragma unroll
        for (int i = 0; i < 4; i++) a[i] = Xs[(ty * 4 + i) * 68 + k];
        const float4 b0 = *(const float4*)&Ws[k * 128 + tx * 8 + 0];
        const float4 b1 = *(const float4*)&Ws[k * 128 + tx * 8 + 4];
        float b[8] = {b0.x, b0.y, b0.z, b0.w, b1.x, b1.y, b1.z, b1.w};
        #pragma unroll
        for (int i = 0; i < 4; i++)
            #pragma unroll
            for (int j = 0; j < 8; j++)
                acc[i][j] = fmaf(a[i], b[j], acc[i][j]);
    }

    #pragma unroll
    for (int i = 0; i < 4; i++) {
        int n = n0 + ty * 4 + i;
        if (n >= NN) continue;
        *(float4*)&g_PX[n * 128 + tx * 8 + 0] =
            make_float4(acc[i][0], acc[i][1], acc[i][2], acc[i][3]);
        *(float4*)&g_PX[n * 128 + tx * 8 + 4] =
            make_float4(acc[i][4], acc[i][5], acc[i][6], acc[i][7]);
    }
}

// ---------------------------------------------------------------------------
// Shared smem layout for persistent mma kernels (103168 B)
// ---------------------------------------------------------------------------
constexpr int S_A   = 0;          // A [128][68] row-major (raw fp32)
constexpr int S_B1  = 8704;       // B1frag [pane=kk*16+nn][66]
constexpr int S_B2  = 17152;      // B2frag [pane=kk*8+nn][66]
constexpr int S_EB1 = 25600;      // bias1 [128]
constexpr int S_EB2 = 25728;      // bias2 [64]
constexpr int MMA_SMEM_BYTES = 25792 * 4;

// ---------------------------------------------------------------------------
// Edge kernel — persistent, 128 threads / 4 warps, M=32 per warp.
// Each B-fragment LDS feeds TWO m16 sub-tiles -> B smem traffic halved.
// ---------------------------------------------------------------------------
__global__ void __launch_bounds__(128, 2) edge_kernel(
    const float* __restrict__ edge_attr,
    const int*   __restrict__ edge_index,   // [2][NE]
    const float* __restrict__ eW1,
    const float* __restrict__ eb1,
    const float* __restrict__ eW2,
    const float* __restrict__ eb2,
    float* __restrict__ out_edge)
{
    extern __shared__ float sm[];
    uint32_t* smu = reinterpret_cast<uint32_t*>(sm);
    const uint32_t sbase = smem_u32(sm);

    const int tid  = threadIdx.x;
    const int lane = tid & 31;
    const int w    = tid >> 5;           // 0..3
    const int gr   = lane >> 2;
    const int ct   = lane & 3;
    const int s0   = ct >> 1;
    const int s1   = 2 + (ct >> 1);
    const int sel  = ct & 1;
    const int even = (ct & 1) == 0;
    const int qb   = 4 * (ct >> 1);
    const int rA0  = 32 * w + gr;        // sub-tile 0 rows: rA0, rA0+8
    const int rA1  = rA0 + 16;           // sub-tile 1 rows: rA1, rA1+8

    int tile = blockIdx.x;

    // ---- prologue ----
    {
        int e0 = tile * 128;
        for (int t = tid; t < 2048; t += 128) {
            int row = t >> 4, c4 = (t & 15) << 2;
            CP_ASYNC16(sbase + (S_A + row * 68 + c4) * 4,
                       edge_attr + (size_t)(e0 + row) * 64 + c4);
        }
    }
    CP_COMMIT();

    for (int t = tid; t < 2048; t += 128) {
        int k = t >> 5, n4 = (t & 31) << 2;
        float4 v = *(const float4*)&eW1[k * 128 + n4];
        int pane = (k >> 3) * 16 + (n4 >> 3);
        int j    = (k >> 2) & 1;
        int ln0  = ((n4 & 7) << 2) | (k & 3);
        uint32_t* p = &smu[S_B1 + pane * 66 + j];
        p[(ln0 + 0)  * 2] = f32_to_tf32(v.x);
        p[(ln0 + 4)  * 2] = f32_to_tf32(v.y);
        p[(ln0 + 8)  * 2] = f32_to_tf32(v.z);
        p[(ln0 + 12) * 2] = f32_to_tf32(v.w);
    }
    for (int t = tid; t < 2048; t += 128) {
        int k = t >> 4, n4 = (t & 15) << 2;
        float4 v = *(const float4*)&eW2[k * 64 + n4];
        int pane = (k >> 3) * 8 + (n4 >> 3);
        int j    = (k >> 2) & 1;
        int ln0  = ((n4 & 7) << 2) | (k & 3);
        uint32_t* p = &smu[S_B2 + pane * 66 + j];
        p[(ln0 + 0)  * 2] = f32_to_tf32(v.x);
        p[(ln0 + 4)  * 2] = f32_to_tf32(v.y);
        p[(ln0 + 8)  * 2] = f32_to_tf32(v.z);
        p[(ln0 + 12) * 2] = f32_to_tf32(v.w);
    }
    if (tid < 128) sm[S_EB1 + tid] = eb1[tid];
    if (tid < 64)  sm[S_EB2 + tid] = eb2[tid];

    CP_WAIT0();
    __syncthreads();

    // ---- persistent tile loop ----
    for (; tile < NTILES; tile += PGRID) {
        const int e0 = tile * 128;

        const int re00 = edge_index[e0 + rA0];
        const int re01 = edge_index[e0 + rA0 + 8];
        const int re10 = edge_index[e0 + rA1];
        const int re11 = edge_index[e0 + rA1 + 8];
        const int ce00 = edge_index[NE + e0 + rA0];
        const int ce01 = edge_index[NE + e0 + rA0 + 8];
        const int ce10 = edge_index[NE + e0 + rA1];
        const int ce11 = edge_index[NE + e0 + rA1 + 8];

        // ---- layer-1 mma: two M=16 sub-tiles share every B load ----
        float acc0[16][4], acc1[16][4];
        #pragma unroll
        for (int nn = 0; nn < 16; nn++) {
            acc0[nn][0] = acc0[nn][1] = acc0[nn][2] = acc0[nn][3] = 0.f;
            acc1[nn][0] = acc1[nn][1] = acc1[nn][2] = acc1[nn][3] = 0.f;
        }
        #pragma unroll
        for (int kk = 0; kk < 8; kk++) {
            const int col = kk * 8 + ct;
            uint32_t a0[4], a1[4];
            a0[0] = smu[S_A + rA0 * 68 + col];
            a0[1] = smu[S_A + (rA0 + 8) * 68 + col];
            a0[2] = smu[S_A + rA0 * 68 + col + 4];
            a0[3] = smu[S_A + (rA0 + 8) * 68 + col + 4];
            a1[0] = smu[S_A + rA1 * 68 + col];
            a1[1] = smu[S_A + (rA1 + 8) * 68 + col];
            a1[2] = smu[S_A + rA1 * 68 + col + 4];
            a1[3] = smu[S_A + (rA1 + 8) * 68 + col + 4];
            #pragma unroll
            for (int nn = 0; nn < 16; nn++) {
                uint32_t b[2];
                const uint2 bv = *(const uint2*)&smu[S_B1 + (kk * 16 + nn) * 66 + lane * 2];
                b[0] = bv.x; b[1] = bv.y;
                mma_tf32(acc0[nn], a0, b);
                mma_tf32(acc1[nn], a1, b);
            }
        }
        __syncthreads();

        // prefetch next A
        {
            int ntile = tile + PGRID;
            if (ntile < NTILES) {
                int ne0 = ntile * 128;
                for (int t = tid; t < 2048; t += 128) {
                    int row = t >> 4, c4 = (t & 15) << 2;
                    CP_ASYNC16(sbase + (S_A + row * 68 + c4) * 4,
                               edge_attr + (size_t)(ne0 + row) * 64 + c4);
                }
            }
            CP_COMMIT();
        }

        // ---- epilogue: H = rna(relu(C1 + PR + PC + eb1)) for both sub-tiles ----
        {
            const float* PR00 = g_PR + (size_t)re00 * 128;
            const float* PR01 = g_PR + (size_t)re01 * 128;
            const float* PC00 = g_PC + (size_t)ce00 * 128;
            const float* PC01 = g_PC + (size_t)ce01 * 128;
            const float* PR10 = g_PR + (size_t)re10 * 128;
            const float* PR11 = g_PR + (size_t)re11 * 128;
            const float* PC10 = g_PC + (size_t)ce10 * 128;
            const float* PC11 = g_PC + (size_t)ce11 * 128;
            #pragma unroll
            for (int nn = 0; nn < 16; nn++) {
                int c = nn * 8 + 2 * ct;
                float2 bb = *(const float2*)&sm[S_EB1 + c];
                {
                    float2 p1 = *(const float2*)&PR00[c];
                    float2 q1 = *(const float2*)&PC00[c];
                    float2 p2 = *(const float2*)&PR01[c];
                    float2 q2 = *(const float2*)&PC01[c];
                    float v0 = acc0[nn][0] + p1.x + q1.x + bb.x;
                    float v1 = acc0[nn][1] + p1.y + q1.y + bb.y;
                    float v2 = acc0[nn][2] + p2.x + q2.x + bb.x;
                    float v3 = acc0[nn][3] + p2.y + q2.y + bb.y;
                    acc0[nn][0] = __uint_as_float(f32_to_tf32(fmaxf(v0, 0.f)));
                    acc0[nn][1] = __uint_as_float(f32_to_tf32(fmaxf(v1, 0.f)));
                    acc0[nn][2] = __uint_as_float(f32_to_tf32(fmaxf(v2, 0.f)));
                    acc0[nn][3] = __uint_as_float(f32_to_tf32(fmaxf(v3, 0.f)));
                }
                {
                    float2 p1 = *(const float2*)&PR10[c];
                    float2 q1 = *(const float2*)&PC10[c];
                    float2 p2 = *(const float2*)&PR11[c];
                    float2 q2 = *(const float2*)&PC11[c];
                    float v0 = acc1[nn][0] + p1.x + q1.x + bb.x;
                    float v1 = acc1[nn][1] + p1.y + q1.y + bb.y;
                    float v2 = acc1[nn][2] + p2.x + q2.x + bb.x;
                    float v3 = acc1[nn][3] + p2.y + q2.y + bb.y;
                    acc1[nn][0] = __uint_as_float(f32_to_tf32(fmaxf(v0, 0.f)));
                    acc1[nn][1] = __uint_as_float(f32_to_tf32(fmaxf(v1, 0.f)));
                    acc1[nn][2] = __uint_as_float(f32_to_tf32(fmaxf(v2, 0.f)));
                    acc1[nn][3] = __uint_as_float(f32_to_tf32(fmaxf(v3, 0.f)));
                }
            }
        }

        // ---- quad-shuffle transpose (both sub-tiles) ----
        #pragma unroll
        for (int kk = 0; kk < 16; kk++) {
            {
                float t0 = __shfl_sync(0xffffffffu, acc0[kk][0], s0, 4);
                float t1 = __shfl_sync(0xffffffffu, acc0[kk][1], s0, 4);
                float t2 = __shfl_sync(0xffffffffu, acc0[kk][2], s0, 4);
                float t3 = __shfl_sync(0xffffffffu, acc0[kk][3], s0, 4);
                float u0 = __shfl_sync(0xffffffffu, acc0[kk][0], s1, 4);
                float u1 = __shfl_sync(0xffffffffu, acc0[kk][1], s1, 4);
                float u2 = __shfl_sync(0xffffffffu, acc0[kk][2], s1, 4);
                float u3 = __shfl_sync(0xffffffffu, acc0[kk][3], s1, 4);
                acc0[kk][0] = sel ? t1 : t0;
                acc0[kk][1] = sel ? t3 : t2;
                acc0[kk][2] = sel ? u1 : u0;
                acc0[kk][3] = sel ? u3 : u2;
            }
            {
                float t0 = __shfl_sync(0xffffffffu, acc1[kk][0], s0, 4);
                float t1 = __shfl_sync(0xffffffffu, acc1[kk][1], s0, 4);
                float t2 = __shfl_sync(0xffffffffu, acc1[kk][2], s0, 4);
                float t3 = __shfl_sync(0xffffffffu, acc1[kk][3], s0, 4);
                float u0 = __shfl_sync(0xffffffffu, acc1[kk][0], s1, 4);
                float u1 = __shfl_sync(0xffffffffu, acc1[kk][1], s1, 4);
                float u2 = __shfl_sync(0xffffffffu, acc1[kk][2], s1, 4);
                float u3 = __shfl_sync(0xffffffffu, acc1[kk][3], s1, 4);
                acc1[kk][0] = sel ? t1 : t0;
                acc1[kk][1] = sel ? t3 : t2;
                acc1[kk][2] = sel ? u1 : u0;
                acc1[kk][3] = sel ? u3 : u2;
            }
        }

        // ---- layer-2 mma: both sub-tiles share every B2 load ----
        float acc20[8][4], acc21[8][4];
        #pragma unroll
        for (int nn = 0; nn < 8; nn++) {
            acc20[nn][0] = acc20[nn][1] = acc20[nn][2] = acc20[nn][3] = 0.f;
            acc21[nn][0] = acc21[nn][1] = acc21[nn][2] = acc21[nn][3] = 0.f;
        }
        #pragma unroll
        for (int kk = 0; kk < 16; kk++) {
            uint32_t a0[4], a1[4];
            a0[0] = __float_as_uint(acc0[kk][0]);
            a0[1] = __float_as_uint(acc0[kk][1]);
            a0[2] = __float_as_uint(acc0[kk][2]);
            a0[3] = __float_as_uint(acc0[kk][3]);
            a1[0] = __float_as_uint(acc1[kk][0]);
            a1[1] = __float_as_uint(acc1[kk][1]);
            a1[2] = __float_as_uint(acc1[kk][2]);
            a1[3] = __float_as_uint(acc1[kk][3]);
            #pragma unroll
            for (int nn = 0; nn < 8; nn++) {
                uint32_t b[2];
                const uint2 bv = *(const uint2*)&smu[S_B2 + (kk * 8 + nn) * 66 + lane * 2];
                b[0] = bv.x; b[1] = bv.y;
                mma_tf32(acc20[nn], a0, b);
                mma_tf32(acc21[nn], a1, b);
            }
        }

        // ---- output: lane-pair exchange -> float4 stores + red.v4 ----
        {
            const int row0 = even ? rA0 : rA0 + 8;
            const int row1 = even ? rA1 : rA1 + 8;
            const int ced0 = even ? ce00 : ce01;
            const int ced1 = even ? ce10 : ce11;
            float* op0 = out_edge + (size_t)(e0 + row0) * 64;
            float* op1 = out_edge + (size_t)(e0 + row1) * 64;
            float* mp0 = g_msg + (size_t)ced0 * 64;
            float* mp1 = g_msg + (size_t)ced1 * 64;
            #pragma unroll
            for (int nn = 0; nn < 8; nn++) {
                int base = nn * 8 + qb;
                float4 bb = *(const float4*)&sm[S_EB2 + base];
                {
                    float sa = __shfl_xor_sync(0xffffffffu, acc20[nn][0], 1);
                    float sb = __shfl_xor_sync(0xffffffffu, acc20[nn][1], 1);
                    float sc = __shfl_xor_sync(0xffffffffu, acc20[nn][2], 1);
                    float sd = __shfl_xor_sync(0xffffffffu, acc20[nn][3], 1);
                    float4 o;
                    if (even) {
                        o = make_float4(acc20[nn][0] + bb.x, acc20[nn][1] + bb.y,
                                        sa + bb.z, sb + bb.w);
                    } else {
                        o = make_float4(sc + bb.x, sd + bb.y,
                                        acc20[nn][2] + bb.z, acc20[nn][3] + bb.w);
                    }
                    *(float4*)(op0 + base) = o;
                    asm volatile("red.global.add.v4.f32 [%0], {%1,%2,%3,%4};"
                                 :: "l"(mp0 + base), "f"(o.x), "f"(o.y), "f"(o.z), "f"(o.w)
                                 : "memory");
                }
                {
                    float sa = __shfl_xor_sync(0xffffffffu, acc21[nn][0], 1);
                    float sb = __shfl_xor_sync(0xffffffffu, acc21[nn][1], 1);
                    float sc = __shfl_xor_sync(0xffffffffu, acc21[nn][2], 1);
                    float sd = __shfl_xor_sync(0xffffffffu, acc21[nn][3], 1);
                    float4 o;
                    if (even) {
                        o = make_float4(acc21[nn][0] + bb.x, acc21[nn][1] + bb.y,
                                        sa + bb.z, sb + bb.w);
                    } else {
                        o = make_float4(sc + bb.x, sd + bb.y,
                                        acc21[nn][2] + bb.z, acc21[nn][3] + bb.w);
                    }
                    *(float4*)(op1 + base) = o;
                    asm volatile("red.global.add.v4.f32 [%0], {%1,%2,%3,%4};"
                                 :: "l"(mp1 + base), "f"(o.x), "f"(o.y), "f"(o.z), "f"(o.w)
                                 : "memory");
                }
            }
        }

        CP_WAIT0();
        __syncthreads();
    }
}

// ---------------------------------------------------------------------------
// Node kernel — persistent tf32 mma (256 threads, M=16/warp), no atomics.
// ---------------------------------------------------------------------------
__global__ void __launch_bounds__(256, 2) node_kernel(
    const float* __restrict__ nW1, const float* __restrict__ nb1,
    const float* __restrict__ nW2, const float* __restrict__ nb2,
    float* __restrict__ out_node)
{
    extern __shared__ float sm[];
    uint32_t* smu = reinterpret_cast<uint32_t*>(sm);
    const uint32_t sbase = smem_u32(sm);

    const int tid  = threadIdx.x;
    const int lane = tid & 31;
    const int w    = tid >> 5;
    const int gr   = lane >> 2;
    const int ct   = lane & 3;
    const int s0   = ct >> 1;
    const int s1   = 2 + (ct >> 1);
    const int sel  = ct & 1;
    const int even = (ct & 1) == 0;
    const int qb   = 4 * (ct >> 1);
    const int r1   = 16 * w + gr;
    const int r2   = r1 + 8;

    int tile = blockIdx.x;

    {
        int n0 = tile * 128;
        for (int t = tid; t < 2048; t += 256) {
            int row = t >> 4, c4 = (t & 15) << 2;
            uint32_t nbytes = (n0 + row < NN) ? 16u : 0u;
            const float* src = g_msg + (size_t)min(n0 + row, NN - 1) * 64 + c4;
            CP_ASYNC16_Z(sbase + (S_A + row * 68 + c4) * 4, src, nbytes);
        }
    }
    CP_COMMIT();

    for (int t = tid; t < 2048; t += 256) {
        int k = t >> 5, n4 = (t & 31) << 2;
        float4 v = *(const float4*)&nW1[(64 + k) * 128 + n4];
        int pane = (k >> 3) * 16 + (n4 >> 3);
        int j    = (k >> 2) & 1;
        int ln0  = ((n4 & 7) << 2) | (k & 3);
        uint32_t* p = &smu[S_B1 + pane * 66 + j];
        p[(ln0 + 0)  * 2] = f32_to_tf32(v.x);
        p[(ln0 + 4)  * 2] = f32_to_tf32(v.y);
        p[(ln0 + 8)  * 2] = f32_to_tf32(v.z);
        p[(ln0 + 12) * 2] = f32_to_tf32(v.w);
    }
    for (int t = tid; t < 2048; t += 256) {
        int k = t >> 4, n4 = (t & 15) << 2;
        float4 v = *(const float4*)&nW2[k * 64 + n4];
        int pane = (k >> 3) * 8 + (n4 >> 3);
        int j    = (k >> 2) & 1;
        int ln0  = ((n4 & 7) << 2) | (k & 3);
        uint32_t* p = &smu[S_B2 + pane * 66 + j];
        p[(ln0 + 0)  * 2] = f32_to_tf32(v.x);
        p[(ln0 + 4)  * 2] = f32_to_tf32(v.y);
        p[(ln0 + 8)  * 2] = f32_to_tf32(v.z);
        p[(ln0 + 12) * 2] = f32_to_tf32(v.w);
    }
    if (tid < 128) sm[S_EB1 + tid] = nb1[tid];
    if (tid < 64)  sm[S_EB2 + tid] = nb2[tid];

    CP_WAIT0();
    __syncthreads();

    for (; tile < NTILN; tile += PGRID) {
        const int n0 = tile * 128;

        float acc[16][4];
        #pragma unroll
        for (int nn = 0; nn < 16; nn++) {
            acc[nn][0] = acc[nn][1] = acc[nn][2] = acc[nn][3] = 0.f;
        }
        #pragma unroll
        for (int kk = 0; kk < 8; kk++) {
            uint32_t a[4];
            a[0] = smu[S_A + r1 * 68 + kk * 8 + ct];
            a[1] = smu[S_A + r2 * 68 + kk * 8 + ct];
            a[2] = smu[S_A + r1 * 68 + kk * 8 + ct + 4];
            a[3] = smu[S_A + r2 * 68 + kk * 8 + ct + 4];
            #pragma unroll
            for (int nn = 0; nn < 16; nn++) {
                uint32_t b[2];
                const uint2 bv = *(const uint2*)&smu[S_B1 + (kk * 16 + nn) * 66 + lane * 2];
                b[0] = bv.x; b[1] = bv.y;
                mma_tf32(acc[nn], a, b);
            }
        }
        __syncthreads();

        {
            int ntile = tile + PGRID;
            if (ntile < NTILN) {
                int nn0 = ntile * 128;
                for (int t = tid; t < 2048; t += 256) {
                    int row = t >> 4, c4 = (t & 15) << 2;
                    uint32_t nbytes = (nn0 + row < NN) ? 16u : 0u;
                    const float* src = g_msg + (size_t)min(nn0 + row, NN - 1) * 64 + c4;
                    CP_ASYNC16_Z(sbase + (S_A + row * 68 + c4) * 4, src, nbytes);
                }
            }
            CP_COMMIT();
        }

        {
            const float* PX1 = g_PX + (size_t)min(n0 + r1, NN - 1) * 128;
            const float* PX2 = g_PX + (size_t)min(n0 + r2, NN - 1) * 128;
            #pragma unroll
            for (int nn = 0; nn < 16; nn++) {
                int c = nn * 8 + 2 * ct;
                float2 p1 = *(const float2*)&PX1[c];
                float2 p2 = *(const float2*)&PX2[c];
                float2 bb = *(const float2*)&sm[S_EB1 + c];
                float v0 = acc[nn][0] + p1.x + bb.x;
                float v1 = acc[nn][1] + p1.y + bb.y;
                float v2 = acc[nn][2] + p2.x + bb.x;
                float v3 = acc[nn][3] + p2.y + bb.y;
                acc[nn][0] = __uint_as_float(f32_to_tf32(fmaxf(v0, 0.f)));
                acc[nn][1] = __uint_as_float(f32_to_tf32(fmaxf(v1, 0.f)));
                acc[nn][2] = __uint_as_float(f32_to_tf32(fmaxf(v2, 0.f)));
                acc[nn][3] = __uint_as_float(f32_to_tf32(fmaxf(v3, 0.f)));
            }
        }

        #pragma unroll
        for (int kk = 0; kk < 16; kk++) {
            float t0 = __shfl_sync(0xffffffffu, acc[kk][0], s0, 4);
            float t1 = __shfl_sync(0xffffffffu, acc[kk][1], s0, 4);
            float t2 = __shfl_sync(0xffffffffu, acc[kk][2], s0, 4);
            float t3 = __shfl_sync(0xffffffffu, acc[kk][3], s0, 4);
            float u0 = __shfl_sync(0xffffffffu, acc[kk][0], s1, 4);
            float u1 = __shfl_sync(0xffffffffu, acc[kk][1], s1, 4);
            float u2 = __shfl_sync(0xffffffffu, acc[kk][2], s1, 4);
            float u3 = __shfl_sync(0xffffffffu, acc[kk][3], s1, 4);
            acc[kk][0] = sel ? t1 : t0;
            acc[kk][1] = sel ? t3 : t2;
            acc[kk][2] = sel ? u1 : u0;
            acc[kk][3] = sel ? u3 : u2;
        }

        float acc2[8][4];
        #pragma unroll
        for (int nn = 0; nn < 8; nn++) {
            acc2[nn][0] = acc2[nn][1] = acc2[nn][2] = acc2[nn][3] = 0.f;
        }
        #pragma unroll
        for (int kk = 0; kk < 16; kk++) {
            uint32_t a[4];
            a[0] = __float_as_uint(acc[kk][0]);
            a[1] = __float_as_uint(acc[kk][1]);
            a[2] = __float_as_uint(acc[kk][2]);
            a[3] = __float_as_uint(acc[kk][3]);
            #pragma unroll
            for (int nn = 0; nn < 8; nn++) {
                uint32_t b[2];
                const uint2 bv = *(const uint2*)&smu[S_B2 + (kk * 8 + nn) * 66 + lane * 2];
                b[0] = bv.x; b[1] = bv.y;
                mma_tf32(acc2[nn], a, b);
            }
        }

        {
            const int row = even ? r1 : r2;
            const int n   = n0 + row;
            float* op = out_node + (size_t)n * 64;
            #pragma unroll
            for (int nn = 0; nn < 8; nn++) {
                float sa = __shfl_xor_sync(0xffffffffu, acc2[nn][0], 1);
                float sb = __shfl_xor_sync(0xffffffffu, acc2[nn][1], 1);
                float sc = __shfl_xor_sync(0xffffffffu, acc2[nn][2], 1);
                float sd = __shfl_xor_sync(0xffffffffu, acc2[nn][3], 1);
                int base = nn * 8 + qb;
                float4 bb = *(const float4*)&sm[S_EB2 + base];
                float4 o;
                if (even) {
                    o = make_float4(acc2[nn][0] + bb.x, acc2[nn][1] + bb.y,
                                    sa + bb.z, sb + bb.w);
                } else {
                    o = make_float4(sc + bb.x, sd + bb.y,
                                    acc2[nn][2] + bb.z, acc2[nn][3] + bb.w);
                }
                if (n < NN) *(float4*)(op + base) = o;
            }
        }

        CP_WAIT0();
        __syncthreads();
    }
}

// ---------------------------------------------------------------------------
extern "C" void kernel_launch(void* const* d_in, const int* in_sizes, int n_in,
                              void* d_out, int out_size)
{
    const float* x    = (const float*)d_in[0];
    const int*   ei   = (const int*)  d_in[1];
    const float* ea   = (const float*)d_in[2];
    const float* eW1  = (const float*)d_in[3];
    const float* eb1  = (const float*)d_in[4];
    const float* eW2  = (const float*)d_in[5];
    const float* eb2  = (const float*)d_in[6];
    const float* nW1  = (const float*)d_in[7];
    const float* nb1  = (const float*)d_in[8];
    const float* nW2  = (const float*)d_in[9];
    const float* nb2  = (const float*)d_in[10];

    float* out_node = (float*)d_out;             // [NN, 64]
    float* out_edge = (float*)d_out + NN * ND;   // [NE, 64]

    const int smem_pre = (64 * 68 + 64 * 256) * 4;   // 82944
    const int smem_px  = (64 * 68 + 64 * 128) * 4;   // 50176

    cudaFuncSetAttribute(precompute_kernel,
        cudaFuncAttributeMaxDynamicSharedMemorySize, smem_pre);
    cudaFuncSetAttribute(precompute_px_kernel,
        cudaFuncAttributeMaxDynamicSharedMemorySize, smem_px);
    cudaFuncSetAttribute(edge_kernel,
        cudaFuncAttributeMaxDynamicSharedMemorySize, MMA_SMEM_BYTES);
    cudaFuncSetAttribute(node_kernel,
        cudaFuncAttributeMaxDynamicSharedMemorySize, MMA_SMEM_BYTES);

    zero_msg_kernel<<<(NN * ED / 4) / 256, 256>>>();
    precompute_kernel<<<(NN + 63) / 64, 256, smem_pre>>>(x, eW1);
    precompute_px_kernel<<<(NN + 63) / 64, 256, smem_px>>>(x, nW1);
    edge_kernel<<<PGRID, 128, MMA_SMEM_BYTES>>>(ea, ei, eW1, eb1, eW2, eb2, out_edge);
    node_kernel<<<PGRID, 256, MMA_SMEM_BYTES>>>(nW1, nb1, nW2, nb2, out_node);
}